// round 8
// baseline (speedup 1.0000x reference)
#include <cuda_runtime.h>
#include <cstdint>
#include <cstddef>

#define NN    100000
#define IND   128
#define HID   64
#define OUTD  128
#define ECAP  1700000
#define SCAN_B 256
#define NPART ((NN + SCAN_B - 1) / SCAN_B)   // 391

// Scratch (device globals — no allocation allowed)
__device__ __align__(16) float g_y1[(size_t)NN * HID];   // x @ w1_l
__device__ __align__(16) float g_xr[(size_t)NN * HID];   // x @ w1_r
__device__ __align__(16) float g_h [(size_t)NN * HID];   // layer-1 activations
__device__ __align__(16) float g_mh[(size_t)NN * HID];   // mean of h over neighbors
__device__ __align__(16) float g_rinv[NN];               // 1 / max(deg, 1)
__device__ __align__(16) int   g_deg[NN];
__device__ int   g_cur[NN];
__device__ int   g_off[NN + 1];
__device__ int   g_part[NPART];
__device__ int   g_poff[NPART];
__device__ int   g_eidx[ECAP];                           // src node per CSR slot

// ---- Blackwell packed f32x2 helpers ----------------------------------------
__device__ __forceinline__ unsigned long long ffma2(
    unsigned long long a, unsigned long long b, unsigned long long c) {
    unsigned long long d;
    asm("fma.rn.f32x2 %0, %1, %2, %3;" : "=l"(d) : "l"(a), "l"(b), "l"(c));
    return d;
}
__device__ __forceinline__ unsigned long long fadd2(
    unsigned long long a, unsigned long long b) {
    unsigned long long d;
    asm("add.rn.f32x2 %0, %1, %2;" : "=l"(d) : "l"(a), "l"(b));
    return d;
}
__device__ __forceinline__ unsigned long long pack2(float lo, float hi) {
    unsigned long long v;
    asm("mov.b64 %0, {%1, %2};" : "=l"(v) : "f"(lo), "f"(hi));
    return v;
}
__device__ __forceinline__ float2 unpack2(unsigned long long v) {
    float2 f;
    asm("mov.b64 {%0, %1}, %2;" : "=f"(f.x), "=f"(f.y) : "l"(v));
    return f;
}

// ---------------------------------------------------------------------------
__global__ void k_init() {
    int i = blockIdx.x * blockDim.x + threadIdx.x;
    if (i < NN) { g_deg[i] = 0; g_cur[i] = 0; }
}

__global__ void k_deg(const int* __restrict__ dst, int E) {
    int e = blockIdx.x * blockDim.x + threadIdx.x;
    if (e < E) {
        int d = dst[e];
        if (d >= 0 && d < NN) atomicAdd(&g_deg[d], 1);
    }
}

// ---------------------------------------------------------------------------
// Multi-block scan (3 phases, all full-grid)
// ---------------------------------------------------------------------------
__global__ __launch_bounds__(SCAN_B) void k_scan_part() {
    __shared__ int sred[SCAN_B];
    int t = threadIdx.x;
    int i = blockIdx.x * SCAN_B + t;
    sred[t] = (i < NN) ? g_deg[i] : 0;
    __syncthreads();
#pragma unroll
    for (int s = SCAN_B / 2; s > 0; s >>= 1) {
        if (t < s) sred[t] += sred[t + s];
        __syncthreads();
    }
    if (t == 0) g_part[blockIdx.x] = sred[0];
}

__global__ __launch_bounds__(512) void k_scan_top() {
    __shared__ int ss[512];
    int t = threadIdx.x;
    ss[t] = (t < NPART) ? g_part[t] : 0;
    __syncthreads();
#pragma unroll
    for (int d = 1; d < 512; d <<= 1) {
        int v = (t >= d) ? ss[t - d] : 0;
        __syncthreads();
        ss[t] += v;
        __syncthreads();
    }
    if (t < NPART) g_poff[t] = (t == 0) ? 0 : ss[t - 1];
}

__global__ __launch_bounds__(SCAN_B) void k_scan_off() {
    __shared__ int ss[SCAN_B];
    int t = threadIdx.x;
    int i = blockIdx.x * SCAN_B + t;
    int d = (i < NN) ? g_deg[i] : 0;
    ss[t] = d;
    __syncthreads();
#pragma unroll
    for (int s = 1; s < SCAN_B; s <<= 1) {
        int v = (t >= s) ? ss[t - s] : 0;
        __syncthreads();
        ss[t] += v;
        __syncthreads();
    }
    if (i < NN) {
        int off = g_poff[blockIdx.x] + ss[t] - d;
        g_off[i] = off;
        g_rinv[i] = 1.0f / fmaxf((float)d, 1.0f);
        if (i == NN - 1) g_off[NN] = off + d;
    }
}

__global__ void k_fill(const int* __restrict__ src,
                       const int* __restrict__ dst, int E) {
    int e = blockIdx.x * blockDim.x + threadIdx.x;
    if (e >= E) return;
    int d = dst[e];
    int s = src[e];
    if (d < 0 || d >= NN || s < 0 || s >= NN) return;
    int pos = g_off[d] + atomicAdd(&g_cur[d], 1);
    if (pos >= 0 && pos < ECAP) g_eidx[pos] = s;
}

// ---------------------------------------------------------------------------
// Layer-1 fused GEMM with packed f32x2 FMA:
//   y1 = x @ w1_l, xr = x @ w1_r   (x:[NN,128], w:[128,64])
// j = warp*16 + lane%16 -> output column (j<64: w1_l, else w1_r);
// kh = lane/16 -> K-half, pair-reduced with shfl_xor(16).
// wc packed as 32 f32x2 pairs; x row loaded as ulonglong2 (no repack).
// ---------------------------------------------------------------------------
__global__ __launch_bounds__(256) void k_gemm1(
    const float* __restrict__ x,
    const float* __restrict__ w1l,
    const float* __restrict__ w1r,
    int n)
{
    int tid  = threadIdx.x;
    int lane = tid & 31;
    int warp = tid >> 5;
    int j    = warp * 16 + (lane & 15);
    int kh   = lane >> 4;

    const float* w = (j < 64) ? w1l : w1r;
    int col = (j < 64) ? j : (j - 64);

    unsigned long long wc[32];
#pragma unroll
    for (int k = 0; k < 32; k++) {
        float wlo = __ldg(&w[(size_t)(kh * 64 + 2 * k)     * 64 + col]);
        float whi = __ldg(&w[(size_t)(kh * 64 + 2 * k + 1) * 64 + col]);
        wc[k] = pack2(wlo, whi);
    }

    for (int i = blockIdx.x; i < n; i += gridDim.x) {
        const ulonglong2* x2 = (const ulonglong2*)(x + (size_t)i * IND + kh * 64);
        unsigned long long a0 = 0ull, a1 = 0ull, a2 = 0ull, a3 = 0ull;
#pragma unroll
        for (int k4 = 0; k4 < 16; k4 += 2) {
            ulonglong2 va = x2[k4];
            ulonglong2 vb = x2[k4 + 1];
            a0 = ffma2(va.x, wc[2 * k4 + 0], a0);
            a1 = ffma2(va.y, wc[2 * k4 + 1], a1);
            a2 = ffma2(vb.x, wc[2 * k4 + 2], a2);
            a3 = ffma2(vb.y, wc[2 * k4 + 3], a3);
        }
        float2 f0 = unpack2(a0), f1 = unpack2(a1);
        float2 f2 = unpack2(a2), f3 = unpack2(a3);
        float acc = ((f0.x + f0.y) + (f1.x + f1.y)) +
                    ((f2.x + f2.y) + (f3.x + f3.y));
        acc += __shfl_xor_sync(0xffffffffu, acc, 16);
        if (kh == 0) {
            if (j < 64) g_y1[(size_t)i * HID + j]        = acc;
            else        g_xr[(size_t)i * HID + (j - 64)] = acc;
        }
    }
}

// ---------------------------------------------------------------------------
// Gather-side aggregation, one warp per node, f32x2 adds.
// 16 lanes x ulonglong2 (16B) cover the 64-float row; half-warps own
// even/odd CSR slots.
// ---------------------------------------------------------------------------
__global__ __launch_bounds__(256) void k_agg(const float* __restrict__ b1,
                                             int layer)
{
    int node = blockIdx.x * 8 + (threadIdx.x >> 5);
    if (node >= NN) return;
    int lane = threadIdx.x & 31;
    int q    = lane & 15;
    int half = lane >> 4;

    const float* val = (layer == 0) ? g_y1 : g_h;
    int beg = g_off[node];
    int end = g_off[node + 1];

    unsigned long long A0 = 0ull, A1 = 0ull, B0 = 0ull, B1 = 0ull;
    int e = beg + half;
    for (; e + 2 < end; e += 4) {
        int s0 = __ldg(&g_eidx[e]);
        int s1 = __ldg(&g_eidx[e + 2]);
        ulonglong2 v0 = ((const ulonglong2*)(val + (size_t)s0 * HID))[q];
        ulonglong2 v1 = ((const ulonglong2*)(val + (size_t)s1 * HID))[q];
        A0 = fadd2(A0, v0.x); A1 = fadd2(A1, v0.y);
        B0 = fadd2(B0, v1.x); B1 = fadd2(B1, v1.y);
    }
    if (e < end) {
        int s = __ldg(&g_eidx[e]);
        ulonglong2 v = ((const ulonglong2*)(val + (size_t)s * HID))[q];
        A0 = fadd2(A0, v.x); A1 = fadd2(A1, v.y);
    }
    unsigned long long S0 = fadd2(A0, B0);
    unsigned long long S1 = fadd2(A1, B1);
    S0 = fadd2(S0, __shfl_xor_sync(0xffffffffu, S0, 16));
    S1 = fadd2(S1, __shfl_xor_sync(0xffffffffu, S1, 16));

    if (half == 0) {
        float2 s0 = unpack2(S0);
        float2 s1 = unpack2(S1);
        float r = g_rinv[node];
        if (layer == 0) {
            float4 xv = ((const float4*)(g_xr + (size_t)node * HID))[q];
            float4 bb = __ldg((const float4*)b1 + q);
            float4 h;
            h.x = fmaxf(fmaf(s0.x, r, bb.x + xv.x), 0.f);
            h.y = fmaxf(fmaf(s0.y, r, bb.y + xv.y), 0.f);
            h.z = fmaxf(fmaf(s1.x, r, bb.z + xv.z), 0.f);
            h.w = fmaxf(fmaf(s1.y, r, bb.w + xv.w), 0.f);
            ((float4*)(g_h + (size_t)node * HID))[q] = h;
        } else {
            float4 m;
            m.x = s0.x * r; m.y = s0.y * r; m.z = s1.x * r; m.w = s1.y * r;
            ((float4*)(g_mh + (size_t)node * HID))[q] = m;
        }
    }
}

// ---------------------------------------------------------------------------
// Layer-2 fused output with packed f32x2 FMA:
//   out = g_mh @ w2_l + b2 + g_h @ w2_r
// ---------------------------------------------------------------------------
__global__ __launch_bounds__(256) void k_out(
    const float* __restrict__ w2l,
    const float* __restrict__ w2r,
    const float* __restrict__ b2,
    float* __restrict__ out,
    int n)
{
    int tid  = threadIdx.x;
    int lane = tid & 31;
    int warp = tid >> 5;
    int j    = warp * 16 + (lane & 15);
    int kh   = lane >> 4;

    const float* w = (kh == 0) ? w2l : w2r;   // [64,128]
    unsigned long long wc[32];
#pragma unroll
    for (int k = 0; k < 32; k++) {
        float wlo = __ldg(&w[(size_t)(2 * k)     * 128 + j]);
        float whi = __ldg(&w[(size_t)(2 * k + 1) * 128 + j]);
        wc[k] = pack2(wlo, whi);
    }

    float bj = __ldg(b2 + j);
    const float* base = (kh == 0) ? g_mh : g_h;

    for (int i = blockIdx.x; i < n; i += gridDim.x) {
        const ulonglong2* s2 = (const ulonglong2*)(base + (size_t)i * HID);
        unsigned long long a0 = 0ull, a1 = 0ull, a2 = 0ull, a3 = 0ull;
#pragma unroll
        for (int k4 = 0; k4 < 16; k4 += 2) {
            ulonglong2 va = s2[k4];
            ulonglong2 vb = s2[k4 + 1];
            a0 = ffma2(va.x, wc[2 * k4 + 0], a0);
            a1 = ffma2(va.y, wc[2 * k4 + 1], a1);
            a2 = ffma2(vb.x, wc[2 * k4 + 2], a2);
            a3 = ffma2(vb.y, wc[2 * k4 + 3], a3);
        }
        float2 f0 = unpack2(a0), f1 = unpack2(a1);
        float2 f2 = unpack2(a2), f3 = unpack2(a3);
        float acc = ((f0.x + f0.y) + (f1.x + f1.y)) +
                    ((f2.x + f2.y) + (f3.x + f3.y));
        acc += __shfl_xor_sync(0xffffffffu, acc, 16);
        if (kh == 0)
            out[(size_t)i * OUTD + j] = acc + bj;
    }
}

// ---------------------------------------------------------------------------
extern "C" void kernel_launch(void* const* d_in, const int* in_sizes, int n_in,
                              void* d_out, int out_size) {
    const float* x   = (const float*)d_in[0];
    const int*   ei  = (const int*)d_in[1];     // int32 edge_index [2, E]
    const float* w1l = (const float*)d_in[2];
    const float* b1  = (const float*)d_in[3];
    const float* w1r = (const float*)d_in[4];
    const float* w2l = (const float*)d_in[5];
    const float* b2  = (const float*)d_in[6];
    const float* w2r = (const float*)d_in[7];
    float* out = (float*)d_out;

    int E = in_sizes[1] / 2;
    const int* src = ei;
    const int* dst = ei + E;

    // CSR build start; k_gemm1 placed as launch #4 so the profiler captures it
    k_init<<<(NN + 511) / 512, 512>>>();
    k_deg <<<(E + 255) / 256, 256>>>(dst, E);
    k_scan_part<<<NPART, SCAN_B>>>();
    k_gemm1<<<888, 256>>>(x, w1l, w1r, NN);       // launch #4 (independent)
    k_scan_top <<<1, 512>>>();
    k_scan_off <<<NPART, SCAN_B>>>();
    k_fill<<<(E + 255) / 256, 256>>>(src, dst, E);

    // Aggregations (gather-side, warp per node)
    k_agg<<<(NN + 7) / 8, 256>>>(b1, 0);
    k_agg<<<(NN + 7) / 8, 256>>>(b1, 1);

    // Output GEMV
    k_out<<<888, 256>>>(w2l, w2r, b2, out, NN);
}

// round 10
// speedup vs baseline: 2.3269x; 2.3269x over previous
#include <cuda_runtime.h>
#include <cstdint>
#include <cstddef>

#define NN    100000
#define IND   128
#define HID   64
#define OUTD  128
#define ECAP  1700000
#define SCAN_B 256
#define NPART ((NN + SCAN_B - 1) / SCAN_B)   // 391

#define BM 64
#define BN 128
#define BK 32

// Scratch (device globals — no allocation allowed)
__device__ __align__(16) float g_yx [(size_t)NN * 128];  // cols 0-63: y1=x@w1l, 64-127: xr=x@w1r
__device__ __align__(16) float g_cat[(size_t)NN * 128];  // cols 0-63: mh, 64-127: h
__device__ __align__(16) float g_rinv[NN];               // 1 / max(deg, 1)
__device__ __align__(16) int   g_deg[NN];
__device__ int   g_cur[NN];
__device__ int   g_off[NN + 1];
__device__ int   g_part[NPART];
__device__ int   g_poff[NPART];
__device__ int   g_eidx[ECAP];                           // src node per CSR slot

// ---------------------------------------------------------------------------
__global__ void k_init() {
    int i = blockIdx.x * blockDim.x + threadIdx.x;
    if (i < NN) { g_deg[i] = 0; g_cur[i] = 0; }
}

__global__ void k_deg(const int* __restrict__ dst, int E) {
    int e = blockIdx.x * blockDim.x + threadIdx.x;
    if (e < E) {
        int d = dst[e];
        if (d >= 0 && d < NN) atomicAdd(&g_deg[d], 1);
    }
}

// ---------------------------------------------------------------------------
// Multi-block scan (3 phases)
// ---------------------------------------------------------------------------
__global__ __launch_bounds__(SCAN_B) void k_scan_part() {
    __shared__ int sred[SCAN_B];
    int t = threadIdx.x;
    int i = blockIdx.x * SCAN_B + t;
    sred[t] = (i < NN) ? g_deg[i] : 0;
    __syncthreads();
#pragma unroll
    for (int s = SCAN_B / 2; s > 0; s >>= 1) {
        if (t < s) sred[t] += sred[t + s];
        __syncthreads();
    }
    if (t == 0) g_part[blockIdx.x] = sred[0];
}

__global__ __launch_bounds__(512) void k_scan_top() {
    __shared__ int ss[512];
    int t = threadIdx.x;
    ss[t] = (t < NPART) ? g_part[t] : 0;
    __syncthreads();
#pragma unroll
    for (int d = 1; d < 512; d <<= 1) {
        int v = (t >= d) ? ss[t - d] : 0;
        __syncthreads();
        ss[t] += v;
        __syncthreads();
    }
    if (t < NPART) g_poff[t] = (t == 0) ? 0 : ss[t - 1];
}

__global__ __launch_bounds__(SCAN_B) void k_scan_off() {
    __shared__ int ss[SCAN_B];
    int t = threadIdx.x;
    int i = blockIdx.x * SCAN_B + t;
    int d = (i < NN) ? g_deg[i] : 0;
    ss[t] = d;
    __syncthreads();
#pragma unroll
    for (int s = 1; s < SCAN_B; s <<= 1) {
        int v = (t >= s) ? ss[t - s] : 0;
        __syncthreads();
        ss[t] += v;
        __syncthreads();
    }
    if (i < NN) {
        int off = g_poff[blockIdx.x] + ss[t] - d;
        g_off[i] = off;
        g_rinv[i] = 1.0f / fmaxf((float)d, 1.0f);
        if (i == NN - 1) g_off[NN] = off + d;
    }
}

__global__ void k_fill(const int* __restrict__ src,
                       const int* __restrict__ dst, int E) {
    int e = blockIdx.x * blockDim.x + threadIdx.x;
    if (e >= E) return;
    int d = dst[e];
    int s = src[e];
    if (d < 0 || d >= NN || s < 0 || s >= NN) return;
    int pos = g_off[d] + atomicAdd(&g_cur[d], 1);
    if (pos >= 0 && pos < ECAP) g_eidx[pos] = s;
}

// ---------------------------------------------------------------------------
// Tiled GEMM: C[n x 128] = A[n x 128] @ W[128 x 128] (+bias)
// Scratch buffers are referenced as device globals INSIDE the kernel — never
// passed from host (host cannot take a __device__ symbol's address; that was
// the R9 bug).
// wmode 0: A = Ain (x),     C = g_yx;  W[k][j] = j<64 ? Wa[k][j] : Wb[k][j-64]
// wmode 1: A = g_cat,       C = Cout;  W[k][j] = k<64 ? Wa[k][j] : Wb[k-64][j], +bias
// BM=64, BN=128, BK=32, 256 threads, 4x8 thread tile.
// ---------------------------------------------------------------------------
__global__ __launch_bounds__(256, 4) void k_mm(
    const float* __restrict__ Ain,
    const float* __restrict__ Wa,
    const float* __restrict__ Wb,
    const float* __restrict__ bias,
    float* __restrict__ Cout,
    int n, int wmode)
{
    __shared__ float As[BK][BM + 4];   // 32 x 68
    __shared__ float Ws[BK][BN];       // 32 x 128

    const float* A = (wmode == 0) ? Ain : g_cat;
    float*       C = (wmode == 0) ? g_yx : Cout;

    int tid = threadIdx.x;
    int tx = tid & 15;                 // col group: cols tx*8 .. +7
    int ty = tid >> 4;                 // row group: rows ty*4 .. +3
    int m0 = blockIdx.x * BM;

    float acc[4][8];
#pragma unroll
    for (int i = 0; i < 4; i++)
#pragma unroll
        for (int j = 0; j < 8; j++) acc[i][j] = 0.f;

    for (int kc = 0; kc < 128; kc += BK) {
        // Stage A chunk (64 rows x 32 cols), transposed into As[k][r]
#pragma unroll
        for (int l = 0; l < 2; l++) {
            int f = tid + l * 256;     // 0..511
            int r = f >> 3;            // 0..63
            int c4 = f & 7;            // 0..7 (float4 within 32-col chunk)
            int row = m0 + r;
            if (row >= n) row = n - 1;
            float4 v = __ldg((const float4*)(A + (size_t)row * 128 + kc) + c4);
            As[c4 * 4 + 0][r] = v.x;
            As[c4 * 4 + 1][r] = v.y;
            As[c4 * 4 + 2][r] = v.z;
            As[c4 * 4 + 3][r] = v.w;
        }
        // Stage W chunk (32 k x 128 j)
#pragma unroll
        for (int l = 0; l < 4; l++) {
            int f = tid + l * 256;     // 0..1023
            int kk = f >> 5;           // 0..31
            int jc = f & 31;           // 0..31
            int j = jc * 4;
            int kg = kc + kk;
            float4 v;
            if (wmode == 0) {
                v = (j < 64)
                    ? __ldg((const float4*)(Wa + (size_t)kg * 64 + j))
                    : __ldg((const float4*)(Wb + (size_t)kg * 64 + (j - 64)));
            } else {
                v = (kg < 64)
                    ? __ldg((const float4*)(Wa + (size_t)kg * 128 + j))
                    : __ldg((const float4*)(Wb + (size_t)(kg - 64) * 128 + j));
            }
            *(float4*)&Ws[kk][j] = v;
        }
        __syncthreads();

#pragma unroll
        for (int k = 0; k < BK; k++) {
            float4 a  = *(const float4*)&As[k][ty * 4];
            float4 b0 = *(const float4*)&Ws[k][tx * 8];
            float4 b1 = *(const float4*)&Ws[k][tx * 8 + 4];
            float av[4] = {a.x, a.y, a.z, a.w};
            float bv[8] = {b0.x, b0.y, b0.z, b0.w, b1.x, b1.y, b1.z, b1.w};
#pragma unroll
            for (int i = 0; i < 4; i++)
#pragma unroll
                for (int j = 0; j < 8; j++)
                    acc[i][j] = fmaf(av[i], bv[j], acc[i][j]);
        }
        __syncthreads();
    }

    float bv[8] = {0, 0, 0, 0, 0, 0, 0, 0};
    if (wmode == 1) {
        float4 t0 = __ldg((const float4*)(bias + tx * 8));
        float4 t1 = __ldg((const float4*)(bias + tx * 8 + 4));
        bv[0] = t0.x; bv[1] = t0.y; bv[2] = t0.z; bv[3] = t0.w;
        bv[4] = t1.x; bv[5] = t1.y; bv[6] = t1.z; bv[7] = t1.w;
    }
#pragma unroll
    for (int i = 0; i < 4; i++) {
        int row = m0 + ty * 4 + i;
        if (row < n) {
            float4 o0 = make_float4(acc[i][0] + bv[0], acc[i][1] + bv[1],
                                    acc[i][2] + bv[2], acc[i][3] + bv[3]);
            float4 o1 = make_float4(acc[i][4] + bv[4], acc[i][5] + bv[5],
                                    acc[i][6] + bv[6], acc[i][7] + bv[7]);
            *(float4*)(C + (size_t)row * 128 + tx * 8)     = o0;
            *(float4*)(C + (size_t)row * 128 + tx * 8 + 4) = o1;
        }
    }
}

// ---------------------------------------------------------------------------
// Gather-side aggregation, one warp per node (row stride 128).
// layer 0: h  = relu(mean(y1[nbrs]) + b1 + xr)   y1/xr from g_yx -> h into g_cat[64:]
// layer 1: mh = mean(h[nbrs])                    h from g_cat[64:] -> mh into g_cat[0:64]
// ---------------------------------------------------------------------------
__global__ __launch_bounds__(256) void k_agg(const float* __restrict__ b1,
                                             int layer)
{
    int node = blockIdx.x * 8 + (threadIdx.x >> 5);
    if (node >= NN) return;
    int lane = threadIdx.x & 31;
    int q    = lane & 15;     // float4 slot within 64-col region
    int half = lane >> 4;     // even/odd edge stream

    const float* val = (layer == 0) ? g_yx : (g_cat + 64);
    int beg = g_off[node];
    int end = g_off[node + 1];

    float4 A = {0.f, 0.f, 0.f, 0.f};
    float4 B = {0.f, 0.f, 0.f, 0.f};
    int e = beg + half;
    for (; e + 2 < end; e += 4) {
        int s0 = __ldg(&g_eidx[e]);
        int s1 = __ldg(&g_eidx[e + 2]);
        float4 v0 = __ldg((const float4*)(val + (size_t)s0 * 128) + q);
        float4 v1 = __ldg((const float4*)(val + (size_t)s1 * 128) + q);
        A.x += v0.x; A.y += v0.y; A.z += v0.z; A.w += v0.w;
        B.x += v1.x; B.y += v1.y; B.z += v1.z; B.w += v1.w;
    }
    if (e < end) {
        int s = __ldg(&g_eidx[e]);
        float4 v = __ldg((const float4*)(val + (size_t)s * 128) + q);
        A.x += v.x; A.y += v.y; A.z += v.z; A.w += v.w;
    }
    float4 acc;
    acc.x = A.x + B.x; acc.y = A.y + B.y; acc.z = A.z + B.z; acc.w = A.w + B.w;
    acc.x += __shfl_xor_sync(0xffffffffu, acc.x, 16);
    acc.y += __shfl_xor_sync(0xffffffffu, acc.y, 16);
    acc.z += __shfl_xor_sync(0xffffffffu, acc.z, 16);
    acc.w += __shfl_xor_sync(0xffffffffu, acc.w, 16);

    if (half == 0) {
        float r = g_rinv[node];
        if (layer == 0) {
            float4 xv = ((const float4*)(g_yx + (size_t)node * 128 + 64))[q];
            float4 bb = __ldg((const float4*)b1 + q);
            float4 h;
            h.x = fmaxf(fmaf(acc.x, r, bb.x + xv.x), 0.f);
            h.y = fmaxf(fmaf(acc.y, r, bb.y + xv.y), 0.f);
            h.z = fmaxf(fmaf(acc.z, r, bb.z + xv.z), 0.f);
            h.w = fmaxf(fmaf(acc.w, r, bb.w + xv.w), 0.f);
            ((float4*)(g_cat + (size_t)node * 128 + 64))[q] = h;
        } else {
            float4 m;
            m.x = acc.x * r; m.y = acc.y * r; m.z = acc.z * r; m.w = acc.w * r;
            ((float4*)(g_cat + (size_t)node * 128))[q] = m;
        }
    }
}

// ---------------------------------------------------------------------------
extern "C" void kernel_launch(void* const* d_in, const int* in_sizes, int n_in,
                              void* d_out, int out_size) {
    const float* x   = (const float*)d_in[0];
    const int*   ei  = (const int*)d_in[1];     // int32 edge_index [2, E]
    const float* w1l = (const float*)d_in[2];
    const float* b1  = (const float*)d_in[3];
    const float* w1r = (const float*)d_in[4];
    const float* w2l = (const float*)d_in[5];
    const float* b2  = (const float*)d_in[6];
    const float* w2r = (const float*)d_in[7];
    float* out = (float*)d_out;

    int E = in_sizes[1] / 2;
    const int* src = ei;
    const int* dst = ei + E;

    int mgrid = (NN + BM - 1) / BM;   // 1563

    k_init<<<(NN + 511) / 512, 512>>>();
    k_deg <<<(E + 255) / 256, 256>>>(dst, E);
    k_scan_part<<<NPART, SCAN_B>>>();
    // Layer-1 GEMM as launch #4 (independent of CSR; lands in profiler window)
    k_mm<<<mgrid, 256>>>(x, w1l, w1r, nullptr, nullptr, NN, 0);
    k_scan_top <<<1, 512>>>();
    k_scan_off <<<NPART, SCAN_B>>>();
    k_fill<<<(E + 255) / 256, 256>>>(src, dst, E);

    k_agg<<<(NN + 7) / 8, 256>>>(b1, 0);
    k_agg<<<(NN + 7) / 8, 256>>>(b1, 1);

    // Layer-2 GEMM (+bias) straight to output
    k_mm<<<mgrid, 256>>>(g_cat /*ignored on device*/, w2l, w2r, b2, out, NN, 1);
}

// round 11
// speedup vs baseline: 2.9770x; 1.2794x over previous
#include <cuda_runtime.h>
#include <cstdint>
#include <cstddef>

#define NN    100000
#define IND   128
#define HID   64
#define OUTD  128
#define ECAP  1700000
#define SCAN_B 256
#define NPART ((NN + SCAN_B - 1) / SCAN_B)   // 391

#define BM 128
#define BN 128
#define BK 32

// Scratch (device globals — no allocation allowed)
__device__ __align__(16) float g_yx [(size_t)NN * 128];  // cols 0-63: y1=x@w1l, 64-127: xr=x@w1r
__device__ __align__(16) float g_cat[(size_t)NN * 128];  // cols 0-63: mh, 64-127: h
__device__ __align__(16) float g_rinv[NN];               // 1 / max(deg, 1)
__device__ __align__(16) int   g_deg[NN];
__device__ int   g_cur[NN];
__device__ int   g_off[NN + 1];
__device__ int   g_part[NPART];
__device__ int   g_poff[NPART];
__device__ int   g_eidx[ECAP];                           // src node per CSR slot

// ---------------------------------------------------------------------------
__global__ void k_init() {
    int i = blockIdx.x * blockDim.x + threadIdx.x;
    if (i < NN) { g_deg[i] = 0; g_cur[i] = 0; }
}

__global__ void k_deg(const int* __restrict__ dst, int E) {
    int e = blockIdx.x * blockDim.x + threadIdx.x;
    if (e < E) {
        int d = dst[e];
        if (d >= 0 && d < NN) atomicAdd(&g_deg[d], 1);
    }
}

// ---------------------------------------------------------------------------
// Multi-block scan (3 phases)
// ---------------------------------------------------------------------------
__global__ __launch_bounds__(SCAN_B) void k_scan_part() {
    __shared__ int sred[SCAN_B];
    int t = threadIdx.x;
    int i = blockIdx.x * SCAN_B + t;
    sred[t] = (i < NN) ? g_deg[i] : 0;
    __syncthreads();
#pragma unroll
    for (int s = SCAN_B / 2; s > 0; s >>= 1) {
        if (t < s) sred[t] += sred[t + s];
        __syncthreads();
    }
    if (t == 0) g_part[blockIdx.x] = sred[0];
}

__global__ __launch_bounds__(512) void k_scan_top() {
    __shared__ int ss[512];
    int t = threadIdx.x;
    ss[t] = (t < NPART) ? g_part[t] : 0;
    __syncthreads();
#pragma unroll
    for (int d = 1; d < 512; d <<= 1) {
        int v = (t >= d) ? ss[t - d] : 0;
        __syncthreads();
        ss[t] += v;
        __syncthreads();
    }
    if (t < NPART) g_poff[t] = (t == 0) ? 0 : ss[t - 1];
}

__global__ __launch_bounds__(SCAN_B) void k_scan_off() {
    __shared__ int ss[SCAN_B];
    int t = threadIdx.x;
    int i = blockIdx.x * SCAN_B + t;
    int d = (i < NN) ? g_deg[i] : 0;
    ss[t] = d;
    __syncthreads();
#pragma unroll
    for (int s = 1; s < SCAN_B; s <<= 1) {
        int v = (t >= s) ? ss[t - s] : 0;
        __syncthreads();
        ss[t] += v;
        __syncthreads();
    }
    if (i < NN) {
        int off = g_poff[blockIdx.x] + ss[t] - d;
        g_off[i] = off;
        g_rinv[i] = 1.0f / fmaxf((float)d, 1.0f);
        if (i == NN - 1) g_off[NN] = off + d;
    }
}

__global__ void k_fill(const int* __restrict__ src,
                       const int* __restrict__ dst, int E) {
    int e = blockIdx.x * blockDim.x + threadIdx.x;
    if (e >= E) return;
    int d = dst[e];
    int s = src[e];
    if (d < 0 || d >= NN || s < 0 || s >= NN) return;
    int pos = g_off[d] + atomicAdd(&g_cur[d], 1);
    if (pos >= 0 && pos < ECAP) g_eidx[pos] = s;
}

// ---------------------------------------------------------------------------
// Tiled GEMM: C[n x 128] = A[n x 128] @ W[128 x 128] (+bias)
// BM=128, BN=128, BK=32, 256 threads, 8x8 thread tile (1.0 B LDS per FMA —
// the R10 4x8 tile was crossbar-bound at 1.5 B/FMA, L1=71.9%).
// Scratch selected via wmode INSIDE the kernel (device globals; R9 lesson).
// wmode 0: A = Ain (x),  C = g_yx;  W[k][j] = j<64 ? Wa[k][j] : Wb[k][j-64]
// wmode 1: A = g_cat,    C = Cout;  W[k][j] = k<64 ? Wa[k][j] : Wb[k-64][j], +bias
// ---------------------------------------------------------------------------
__global__ __launch_bounds__(256, 2) void k_mm(
    const float* __restrict__ Ain,
    const float* __restrict__ Wa,
    const float* __restrict__ Wb,
    const float* __restrict__ bias,
    float* __restrict__ Cout,
    int n, int wmode)
{
    __shared__ float As[BK][BM + 4];   // 32 x 132, A staged transposed
    __shared__ float Ws[BK][BN];       // 32 x 128

    const float* A = (wmode == 0) ? Ain : g_cat;
    float*       C = (wmode == 0) ? g_yx : Cout;

    int tid = threadIdx.x;
    int tx = tid & 15;                 // col group: cols tx*8 .. +7
    int ty = tid >> 4;                 // row group: rows ty*8 .. +7
    int m0 = blockIdx.x * BM;

    float acc[8][8];
#pragma unroll
    for (int i = 0; i < 8; i++)
#pragma unroll
        for (int j = 0; j < 8; j++) acc[i][j] = 0.f;

    for (int kc = 0; kc < 128; kc += BK) {
        // Stage A chunk (128 rows x 32 cols), transposed into As[k][r]
#pragma unroll
        for (int l = 0; l < 4; l++) {
            int f = tid + l * 256;     // 0..1023
            int r = f >> 3;            // 0..127
            int c4 = f & 7;            // float4 index within 32-col chunk
            int row = m0 + r;
            if (row >= n) row = n - 1;
            float4 v = __ldg((const float4*)(A + (size_t)row * 128 + kc) + c4);
            As[c4 * 4 + 0][r] = v.x;
            As[c4 * 4 + 1][r] = v.y;
            As[c4 * 4 + 2][r] = v.z;
            As[c4 * 4 + 3][r] = v.w;
        }
        // Stage W chunk (32 k x 128 j)
#pragma unroll
        for (int l = 0; l < 4; l++) {
            int f = tid + l * 256;     // 0..1023
            int kk = f >> 5;           // 0..31
            int jc = f & 31;           // 0..31
            int j = jc * 4;
            int kg = kc + kk;
            float4 v;
            if (wmode == 0) {
                v = (j < 64)
                    ? __ldg((const float4*)(Wa + (size_t)kg * 64 + j))
                    : __ldg((const float4*)(Wb + (size_t)kg * 64 + (j - 64)));
            } else {
                v = (kg < 64)
                    ? __ldg((const float4*)(Wa + (size_t)kg * 128 + j))
                    : __ldg((const float4*)(Wb + (size_t)(kg - 64) * 128 + j));
            }
            *(float4*)&Ws[kk][j] = v;
        }
        __syncthreads();

#pragma unroll
        for (int k = 0; k < BK; k++) {
            float4 a0 = *(const float4*)&As[k][ty * 8];
            float4 a1 = *(const float4*)&As[k][ty * 8 + 4];
            float4 b0 = *(const float4*)&Ws[k][tx * 8];
            float4 b1 = *(const float4*)&Ws[k][tx * 8 + 4];
            float av[8] = {a0.x, a0.y, a0.z, a0.w, a1.x, a1.y, a1.z, a1.w};
            float bv[8] = {b0.x, b0.y, b0.z, b0.w, b1.x, b1.y, b1.z, b1.w};
#pragma unroll
            for (int i = 0; i < 8; i++)
#pragma unroll
                for (int j = 0; j < 8; j++)
                    acc[i][j] = fmaf(av[i], bv[j], acc[i][j]);
        }
        __syncthreads();
    }

    float bv[8] = {0, 0, 0, 0, 0, 0, 0, 0};
    if (wmode == 1) {
        float4 t0 = __ldg((const float4*)(bias + tx * 8));
        float4 t1 = __ldg((const float4*)(bias + tx * 8 + 4));
        bv[0] = t0.x; bv[1] = t0.y; bv[2] = t0.z; bv[3] = t0.w;
        bv[4] = t1.x; bv[5] = t1.y; bv[6] = t1.z; bv[7] = t1.w;
    }
#pragma unroll
    for (int i = 0; i < 8; i++) {
        int row = m0 + ty * 8 + i;
        if (row < n) {
            float4 o0 = make_float4(acc[i][0] + bv[0], acc[i][1] + bv[1],
                                    acc[i][2] + bv[2], acc[i][3] + bv[3]);
            float4 o1 = make_float4(acc[i][4] + bv[4], acc[i][5] + bv[5],
                                    acc[i][6] + bv[6], acc[i][7] + bv[7]);
            *(float4*)(C + (size_t)row * 128 + tx * 8)     = o0;
            *(float4*)(C + (size_t)row * 128 + tx * 8 + 4) = o1;
        }
    }
}

// ---------------------------------------------------------------------------
// Gather-side aggregation, one warp per node (row stride 128).
// layer 0: h  = relu(mean(y1[nbrs]) + b1 + xr)   y1/xr from g_yx -> h into g_cat[64:]
// layer 1: mh = mean(h[nbrs])                    h from g_cat[64:] -> mh into g_cat[0:64]
// ---------------------------------------------------------------------------
__global__ __launch_bounds__(256) void k_agg(const float* __restrict__ b1,
                                             int layer)
{
    int node = blockIdx.x * 8 + (threadIdx.x >> 5);
    if (node >= NN) return;
    int lane = threadIdx.x & 31;
    int q    = lane & 15;     // float4 slot within 64-col region
    int half = lane >> 4;     // even/odd edge stream

    const float* val = (layer == 0) ? g_yx : (g_cat + 64);
    int beg = g_off[node];
    int end = g_off[node + 1];

    float4 A = {0.f, 0.f, 0.f, 0.f};
    float4 B = {0.f, 0.f, 0.f, 0.f};
    int e = beg + half;
    for (; e + 2 < end; e += 4) {
        int s0 = __ldg(&g_eidx[e]);
        int s1 = __ldg(&g_eidx[e + 2]);
        float4 v0 = __ldg((const float4*)(val + (size_t)s0 * 128) + q);
        float4 v1 = __ldg((const float4*)(val + (size_t)s1 * 128) + q);
        A.x += v0.x; A.y += v0.y; A.z += v0.z; A.w += v0.w;
        B.x += v1.x; B.y += v1.y; B.z += v1.z; B.w += v1.w;
    }
    if (e < end) {
        int s = __ldg(&g_eidx[e]);
        float4 v = __ldg((const float4*)(val + (size_t)s * 128) + q);
        A.x += v.x; A.y += v.y; A.z += v.z; A.w += v.w;
    }
    float4 acc;
    acc.x = A.x + B.x; acc.y = A.y + B.y; acc.z = A.z + B.z; acc.w = A.w + B.w;
    acc.x += __shfl_xor_sync(0xffffffffu, acc.x, 16);
    acc.y += __shfl_xor_sync(0xffffffffu, acc.y, 16);
    acc.z += __shfl_xor_sync(0xffffffffu, acc.z, 16);
    acc.w += __shfl_xor_sync(0xffffffffu, acc.w, 16);

    if (half == 0) {
        float r = g_rinv[node];
        if (layer == 0) {
            float4 xv = ((const float4*)(g_yx + (size_t)node * 128 + 64))[q];
            float4 bb = __ldg((const float4*)b1 + q);
            float4 h;
            h.x = fmaxf(fmaf(acc.x, r, bb.x + xv.x), 0.f);
            h.y = fmaxf(fmaf(acc.y, r, bb.y + xv.y), 0.f);
            h.z = fmaxf(fmaf(acc.z, r, bb.z + xv.z), 0.f);
            h.w = fmaxf(fmaf(acc.w, r, bb.w + xv.w), 0.f);
            ((float4*)(g_cat + (size_t)node * 128 + 64))[q] = h;
        } else {
            float4 m;
            m.x = acc.x * r; m.y = acc.y * r; m.z = acc.z * r; m.w = acc.w * r;
            ((float4*)(g_cat + (size_t)node * 128))[q] = m;
        }
    }
}

// ---------------------------------------------------------------------------
extern "C" void kernel_launch(void* const* d_in, const int* in_sizes, int n_in,
                              void* d_out, int out_size) {
    const float* x   = (const float*)d_in[0];
    const int*   ei  = (const int*)d_in[1];     // int32 edge_index [2, E]
    const float* w1l = (const float*)d_in[2];
    const float* b1  = (const float*)d_in[3];
    const float* w1r = (const float*)d_in[4];
    const float* w2l = (const float*)d_in[5];
    const float* b2  = (const float*)d_in[6];
    const float* w2r = (const float*)d_in[7];
    float* out = (float*)d_out;

    int E = in_sizes[1] / 2;
    const int* src = ei;
    const int* dst = ei + E;

    int mgrid = (NN + BM - 1) / BM;   // 782

    k_init<<<(NN + 511) / 512, 512>>>();
    k_deg <<<(E + 255) / 256, 256>>>(dst, E);
    k_scan_part<<<NPART, SCAN_B>>>();
    // Layer-1 GEMM as launch #4 (independent of CSR; lands in profiler window)
    k_mm<<<mgrid, 256>>>(x, w1l, w1r, nullptr, nullptr, NN, 0);
    k_scan_top <<<1, 512>>>();
    k_scan_off <<<NPART, SCAN_B>>>();
    k_fill<<<(E + 255) / 256, 256>>>(src, dst, E);

    k_agg<<<(NN + 7) / 8, 256>>>(b1, 0);
    k_agg<<<(NN + 7) / 8, 256>>>(b1, 1);

    // Layer-2 GEMM (+bias) straight to output
    k_mm<<<mgrid, 256>>>(nullptr /*A=g_cat via wmode*/, w2l, w2r, b2, out, NN, 1);
}

// round 12
// speedup vs baseline: 4.5832x; 1.5396x over previous
#include <cuda_runtime.h>
#include <cstdint>
#include <cstddef>

#define NN    100000
#define IND   128
#define HID   64
#define OUTD  128
#define ECAP  1700000
#define SCAN_B 256
#define NPART ((NN + SCAN_B - 1) / SCAN_B)   // 391

#define BM 128
#define BN 128
#define BK 32

// Scratch (device globals — no allocation allowed)
__device__ __align__(16) float g_yx [(size_t)NN * 128];  // cols 0-63: y1=x@w1l, 64-127: xr=x@w1r
__device__ __align__(16) float g_cat[(size_t)NN * 128];  // cols 0-63: mh, 64-127: h
__device__ __align__(16) float g_rinv[NN];               // 1 / max(deg, 1)
__device__ __align__(16) int   g_deg[NN];
__device__ int   g_cur[NN];
__device__ int   g_off[NN + 1];
__device__ int   g_part[NPART];
__device__ int   g_poff[NPART];
__device__ int   g_eidx[ECAP];                           // src node per CSR slot

// ---------------------------------------------------------------------------
__device__ __forceinline__ float cvt_tf32(float x) {
    uint32_t u;
    asm("cvt.rna.tf32.f32 %0, %1;" : "=r"(u) : "f"(x));
    return __uint_as_float(u);
}

__device__ __forceinline__ void mma_tf32(float* d, const uint32_t* a,
                                         const uint32_t* b) {
    asm("mma.sync.aligned.m16n8k8.row.col.f32.tf32.tf32.f32 "
        "{%0,%1,%2,%3}, {%4,%5,%6,%7}, {%8,%9}, {%0,%1,%2,%3};"
        : "+f"(d[0]), "+f"(d[1]), "+f"(d[2]), "+f"(d[3])
        : "r"(a[0]), "r"(a[1]), "r"(a[2]), "r"(a[3]),
          "r"(b[0]), "r"(b[1]));
}

// ---------------------------------------------------------------------------
__global__ void k_init() {
    int i = blockIdx.x * blockDim.x + threadIdx.x;
    if (i < NN) { g_deg[i] = 0; g_cur[i] = 0; }
}

__global__ void k_deg(const int* __restrict__ dst, int E) {
    int e = blockIdx.x * blockDim.x + threadIdx.x;
    if (e < E) {
        int d = dst[e];
        if (d >= 0 && d < NN) atomicAdd(&g_deg[d], 1);
    }
}

// ---------------------------------------------------------------------------
// Multi-block scan (3 phases)
// ---------------------------------------------------------------------------
__global__ __launch_bounds__(SCAN_B) void k_scan_part() {
    __shared__ int sred[SCAN_B];
    int t = threadIdx.x;
    int i = blockIdx.x * SCAN_B + t;
    sred[t] = (i < NN) ? g_deg[i] : 0;
    __syncthreads();
#pragma unroll
    for (int s = SCAN_B / 2; s > 0; s >>= 1) {
        if (t < s) sred[t] += sred[t + s];
        __syncthreads();
    }
    if (t == 0) g_part[blockIdx.x] = sred[0];
}

__global__ __launch_bounds__(512) void k_scan_top() {
    __shared__ int ss[512];
    int t = threadIdx.x;
    ss[t] = (t < NPART) ? g_part[t] : 0;
    __syncthreads();
#pragma unroll
    for (int d = 1; d < 512; d <<= 1) {
        int v = (t >= d) ? ss[t - d] : 0;
        __syncthreads();
        ss[t] += v;
        __syncthreads();
    }
    if (t < NPART) g_poff[t] = (t == 0) ? 0 : ss[t - 1];
}

__global__ __launch_bounds__(SCAN_B) void k_scan_off() {
    __shared__ int ss[SCAN_B];
    int t = threadIdx.x;
    int i = blockIdx.x * SCAN_B + t;
    int d = (i < NN) ? g_deg[i] : 0;
    ss[t] = d;
    __syncthreads();
#pragma unroll
    for (int s = 1; s < SCAN_B; s <<= 1) {
        int v = (t >= s) ? ss[t - s] : 0;
        __syncthreads();
        ss[t] += v;
        __syncthreads();
    }
    if (i < NN) {
        int off = g_poff[blockIdx.x] + ss[t] - d;
        g_off[i] = off;
        g_rinv[i] = 1.0f / fmaxf((float)d, 1.0f);
        if (i == NN - 1) g_off[NN] = off + d;
    }
}

__global__ void k_fill(const int* __restrict__ src,
                       const int* __restrict__ dst, int E) {
    int e = blockIdx.x * blockDim.x + threadIdx.x;
    if (e >= E) return;
    int d = dst[e];
    int s = src[e];
    if (d < 0 || d >= NN || s < 0 || s >= NN) return;
    int pos = g_off[d] + atomicAdd(&g_cur[d], 1);
    if (pos >= 0 && pos < ECAP) g_eidx[pos] = s;
}

// ---------------------------------------------------------------------------
// Tensor-core GEMM (tf32 mma.sync): C[n x 128] = A[n x 128] @ W[128 x 128]
// 8 warps in 2x4 layout, warp tile 64x32 = 4x4 m16n8k8 fragments.
// tf32 conversion (cvt.rna) happens during smem staging.
// Smem strides: As[m][k] stride 36 (36%32=4 -> 4*grp+qd hits 32 banks),
//               Ws[k][n] stride 136 (136%32=8 -> 8*qd+grp hits 32 banks).
// wmode 0: A = Ain (x),  C = g_yx;  W[k][j] = j<64 ? Wa[k][j] : Wb[k][j-64]
// wmode 1: A = g_cat,    C = Cout;  W[k][j] = k<64 ? Wa[k][j] : Wb[k-64][j], +bias
// ---------------------------------------------------------------------------
__global__ __launch_bounds__(256, 2) void k_mm(
    const float* __restrict__ Ain,
    const float* __restrict__ Wa,
    const float* __restrict__ Wb,
    const float* __restrict__ bias,
    float* __restrict__ Cout,
    int n, int wmode)
{
    __shared__ float As[BM][36];       // [m][k]  128x36x4 = 18.4 KB
    __shared__ float Ws[BK][136];      // [k][n]   32x136x4 = 17.4 KB

    const float* A = (wmode == 0) ? Ain : g_cat;
    float*       C = (wmode == 0) ? g_yx : Cout;

    int tid  = threadIdx.x;
    int wid  = tid >> 5;
    int lane = tid & 31;
    int grp  = lane >> 2;              // 0..7
    int qd   = lane & 3;               // 0..3
    int wm   = (wid >> 2) * 64;        // warp m offset within tile
    int wn   = (wid & 3) * 32;         // warp n offset within tile
    int m0   = blockIdx.x * BM;

    float acc[4][4][4];
#pragma unroll
    for (int i = 0; i < 4; i++)
#pragma unroll
        for (int j = 0; j < 4; j++)
#pragma unroll
            for (int r = 0; r < 4; r++) acc[i][j][r] = 0.f;

    for (int kc = 0; kc < 128; kc += BK) {
        // Stage A: 128 rows x 32 k, tf32-converted, [m][k] layout
#pragma unroll
        for (int l = 0; l < 4; l++) {
            int f = tid + l * 256;     // 0..1023
            int r = f >> 3;            // 0..127
            int c4 = f & 7;            // float4 slot in 32-col chunk
            int row = m0 + r;
            if (row >= n) row = n - 1;
            float4 v = __ldg((const float4*)(A + (size_t)row * 128 + kc) + c4);
            float4 t;
            t.x = cvt_tf32(v.x); t.y = cvt_tf32(v.y);
            t.z = cvt_tf32(v.z); t.w = cvt_tf32(v.w);
            *(float4*)&As[r][c4 * 4] = t;
        }
        // Stage W: 32 k x 128 n, tf32-converted, [k][n] layout
#pragma unroll
        for (int l = 0; l < 4; l++) {
            int f = tid + l * 256;
            int kk = f >> 5;           // 0..31
            int jc = f & 31;
            int j = jc * 4;
            int kg = kc + kk;
            float4 v;
            if (wmode == 0) {
                v = (j < 64)
                    ? __ldg((const float4*)(Wa + (size_t)kg * 64 + j))
                    : __ldg((const float4*)(Wb + (size_t)kg * 64 + (j - 64)));
            } else {
                v = (kg < 64)
                    ? __ldg((const float4*)(Wa + (size_t)kg * 128 + j))
                    : __ldg((const float4*)(Wb + (size_t)(kg - 64) * 128 + j));
            }
            float4 t;
            t.x = cvt_tf32(v.x); t.y = cvt_tf32(v.y);
            t.z = cvt_tf32(v.z); t.w = cvt_tf32(v.w);
            *(float4*)&Ws[kk][j] = t;
        }
        __syncthreads();

#pragma unroll
        for (int kk = 0; kk < BK; kk += 8) {
            uint32_t af[4][4];
#pragma unroll
            for (int mi = 0; mi < 4; mi++) {
                int m = wm + mi * 16;
                af[mi][0] = __float_as_uint(As[m + grp][kk + qd]);
                af[mi][1] = __float_as_uint(As[m + grp + 8][kk + qd]);
                af[mi][2] = __float_as_uint(As[m + grp][kk + qd + 4]);
                af[mi][3] = __float_as_uint(As[m + grp + 8][kk + qd + 4]);
            }
            uint32_t bf[4][2];
#pragma unroll
            for (int ni = 0; ni < 4; ni++) {
                int nn = wn + ni * 8 + grp;
                bf[ni][0] = __float_as_uint(Ws[kk + qd][nn]);
                bf[ni][1] = __float_as_uint(Ws[kk + qd + 4][nn]);
            }
#pragma unroll
            for (int mi = 0; mi < 4; mi++)
#pragma unroll
                for (int ni = 0; ni < 4; ni++)
                    mma_tf32(acc[mi][ni], af[mi], bf[ni]);
        }
        __syncthreads();
    }

    // Epilogue: bias (wmode 1) + store. c0,c1 at (row, col..col+1); c2,c3 at row+8.
    float bb[4][2];
#pragma unroll
    for (int ni = 0; ni < 4; ni++) {
        if (wmode == 1) {
            int c = wn + ni * 8 + qd * 2;
            bb[ni][0] = __ldg(bias + c);
            bb[ni][1] = __ldg(bias + c + 1);
        } else {
            bb[ni][0] = 0.f; bb[ni][1] = 0.f;
        }
    }
#pragma unroll
    for (int mi = 0; mi < 4; mi++) {
        int r0 = m0 + wm + mi * 16 + grp;
        int r1 = r0 + 8;
#pragma unroll
        for (int ni = 0; ni < 4; ni++) {
            int c = wn + ni * 8 + qd * 2;
            if (r0 < n) {
                float2 v0 = make_float2(acc[mi][ni][0] + bb[ni][0],
                                        acc[mi][ni][1] + bb[ni][1]);
                *(float2*)(C + (size_t)r0 * 128 + c) = v0;
            }
            if (r1 < n) {
                float2 v1 = make_float2(acc[mi][ni][2] + bb[ni][0],
                                        acc[mi][ni][3] + bb[ni][1]);
                *(float2*)(C + (size_t)r1 * 128 + c) = v1;
            }
        }
    }
}

// ---------------------------------------------------------------------------
// Gather-side aggregation, one warp per node (row stride 128).
// layer 0: h  = relu(mean(y1[nbrs]) + b1 + xr)   y1/xr from g_yx -> h into g_cat[64:]
// layer 1: mh = mean(h[nbrs])                    h from g_cat[64:] -> mh into g_cat[0:64]
// ---------------------------------------------------------------------------
__global__ __launch_bounds__(256) void k_agg(const float* __restrict__ b1,
                                             int layer)
{
    int node = blockIdx.x * 8 + (threadIdx.x >> 5);
    if (node >= NN) return;
    int lane = threadIdx.x & 31;
    int q    = lane & 15;
    int half = lane >> 4;

    const float* val = (layer == 0) ? g_yx : (g_cat + 64);
    int beg = g_off[node];
    int end = g_off[node + 1];

    float4 A = {0.f, 0.f, 0.f, 0.f};
    float4 B = {0.f, 0.f, 0.f, 0.f};
    int e = beg + half;
    for (; e + 2 < end; e += 4) {
        int s0 = __ldg(&g_eidx[e]);
        int s1 = __ldg(&g_eidx[e + 2]);
        float4 v0 = __ldg((const float4*)(val + (size_t)s0 * 128) + q);
        float4 v1 = __ldg((const float4*)(val + (size_t)s1 * 128) + q);
        A.x += v0.x; A.y += v0.y; A.z += v0.z; A.w += v0.w;
        B.x += v1.x; B.y += v1.y; B.z += v1.z; B.w += v1.w;
    }
    if (e < end) {
        int s = __ldg(&g_eidx[e]);
        float4 v = __ldg((const float4*)(val + (size_t)s * 128) + q);
        A.x += v.x; A.y += v.y; A.z += v.z; A.w += v.w;
    }
    float4 acc;
    acc.x = A.x + B.x; acc.y = A.y + B.y; acc.z = A.z + B.z; acc.w = A.w + B.w;
    acc.x += __shfl_xor_sync(0xffffffffu, acc.x, 16);
    acc.y += __shfl_xor_sync(0xffffffffu, acc.y, 16);
    acc.z += __shfl_xor_sync(0xffffffffu, acc.z, 16);
    acc.w += __shfl_xor_sync(0xffffffffu, acc.w, 16);

    if (half == 0) {
        float r = g_rinv[node];
        if (layer == 0) {
            float4 xv = ((const float4*)(g_yx + (size_t)node * 128 + 64))[q];
            float4 bb = __ldg((const float4*)b1 + q);
            float4 h;
            h.x = fmaxf(fmaf(acc.x, r, bb.x + xv.x), 0.f);
            h.y = fmaxf(fmaf(acc.y, r, bb.y + xv.y), 0.f);
            h.z = fmaxf(fmaf(acc.z, r, bb.z + xv.z), 0.f);
            h.w = fmaxf(fmaf(acc.w, r, bb.w + xv.w), 0.f);
            ((float4*)(g_cat + (size_t)node * 128 + 64))[q] = h;
        } else {
            float4 m;
            m.x = acc.x * r; m.y = acc.y * r; m.z = acc.z * r; m.w = acc.w * r;
            ((float4*)(g_cat + (size_t)node * 128))[q] = m;
        }
    }
}

// ---------------------------------------------------------------------------
extern "C" void kernel_launch(void* const* d_in, const int* in_sizes, int n_in,
                              void* d_out, int out_size) {
    const float* x   = (const float*)d_in[0];
    const int*   ei  = (const int*)d_in[1];     // int32 edge_index [2, E]
    const float* w1l = (const float*)d_in[2];
    const float* b1  = (const float*)d_in[3];
    const float* w1r = (const float*)d_in[4];
    const float* w2l = (const float*)d_in[5];
    const float* b2  = (const float*)d_in[6];
    const float* w2r = (const float*)d_in[7];
    float* out = (float*)d_out;

    int E = in_sizes[1] / 2;
    const int* src = ei;
    const int* dst = ei + E;

    int mgrid = (NN + BM - 1) / BM;   // 782

    k_init<<<(NN + 511) / 512, 512>>>();
    k_deg <<<(E + 255) / 256, 256>>>(dst, E);
    k_scan_part<<<NPART, SCAN_B>>>();
    // Layer-1 GEMM as launch #4 (independent of CSR; lands in profiler window)
    k_mm<<<mgrid, 256>>>(x, w1l, w1r, nullptr, nullptr, NN, 0);
    k_scan_top <<<1, 512>>>();
    k_scan_off <<<NPART, SCAN_B>>>();
    k_fill<<<(E + 255) / 256, 256>>>(src, dst, E);

    k_agg<<<(NN + 7) / 8, 256>>>(b1, 0);
    k_agg<<<(NN + 7) / 8, 256>>>(b1, 1);

    // Layer-2 GEMM (+bias) straight to output
    k_mm<<<mgrid, 256>>>(nullptr /*A=g_cat via wmode*/, w2l, w2r, b2, out, NN, 1);
}

// round 13
// speedup vs baseline: 4.8602x; 1.0604x over previous
#include <cuda_runtime.h>
#include <cuda_fp16.h>
#include <cstdint>
#include <cstddef>

#define NN    100000
#define IND   128
#define HID   64
#define OUTD  128
#define ECAP  1700000
#define SCAN_B 256
#define NPART ((NN + SCAN_B - 1) / SCAN_B)   // 391

#define BM 128
#define BN 128
#define BK 32

// Scratch (device globals — no allocation allowed). Node features in fp16.
__device__ __align__(16) __half g_yx [(size_t)NN * 128]; // 0-63: y1=x@w1l, 64-127: xr=x@w1r
__device__ __align__(16) __half g_cat[(size_t)NN * 128]; // 0-63: mh, 64-127: h
__device__ __align__(16) float g_rinv[NN];
__device__ __align__(16) int   g_deg[NN];
__device__ int   g_cur[NN];                               // seeded with offsets by scan_off
__device__ int   g_off[NN + 1];
__device__ int   g_part[NPART];
__device__ int   g_poff[NPART];
__device__ int   g_eidx[ECAP];

// ---------------------------------------------------------------------------
__device__ __forceinline__ float cvt_tf32(float x) {
    uint32_t u;
    asm("cvt.rna.tf32.f32 %0, %1;" : "=r"(u) : "f"(x));
    return __uint_as_float(u);
}

__device__ __forceinline__ void mma_tf32(float* d, const uint32_t* a,
                                         const uint32_t* b) {
    asm("mma.sync.aligned.m16n8k8.row.col.f32.tf32.tf32.f32 "
        "{%0,%1,%2,%3}, {%4,%5,%6,%7}, {%8,%9}, {%0,%1,%2,%3};"
        : "+f"(d[0]), "+f"(d[1]), "+f"(d[2]), "+f"(d[3])
        : "r"(a[0]), "r"(a[1]), "r"(a[2]), "r"(a[3]),
          "r"(b[0]), "r"(b[1]));
}

// ---------------------------------------------------------------------------
__global__ void k_init() {
    int i = blockIdx.x * blockDim.x + threadIdx.x;
    if (i < NN) g_deg[i] = 0;
}

__global__ void k_deg(const int* __restrict__ dst, int E) {
    int e = blockIdx.x * blockDim.x + threadIdx.x;
    if (e < E) {
        int d = dst[e];
        if (d >= 0 && d < NN) atomicAdd(&g_deg[d], 1);
    }
}

// ---------------------------------------------------------------------------
// Multi-block scan (3 phases)
// ---------------------------------------------------------------------------
__global__ __launch_bounds__(SCAN_B) void k_scan_part() {
    __shared__ int sred[SCAN_B];
    int t = threadIdx.x;
    int i = blockIdx.x * SCAN_B + t;
    sred[t] = (i < NN) ? g_deg[i] : 0;
    __syncthreads();
#pragma unroll
    for (int s = SCAN_B / 2; s > 0; s >>= 1) {
        if (t < s) sred[t] += sred[t + s];
        __syncthreads();
    }
    if (t == 0) g_part[blockIdx.x] = sred[0];
}

__global__ __launch_bounds__(512) void k_scan_top() {
    __shared__ int ss[512];
    int t = threadIdx.x;
    ss[t] = (t < NPART) ? g_part[t] : 0;
    __syncthreads();
#pragma unroll
    for (int d = 1; d < 512; d <<= 1) {
        int v = (t >= d) ? ss[t - d] : 0;
        __syncthreads();
        ss[t] += v;
        __syncthreads();
    }
    if (t < NPART) g_poff[t] = (t == 0) ? 0 : ss[t - 1];
}

__global__ __launch_bounds__(SCAN_B) void k_scan_off() {
    __shared__ int ss[SCAN_B];
    int t = threadIdx.x;
    int i = blockIdx.x * SCAN_B + t;
    int d = (i < NN) ? g_deg[i] : 0;
    ss[t] = d;
    __syncthreads();
#pragma unroll
    for (int s = 1; s < SCAN_B; s <<= 1) {
        int v = (t >= s) ? ss[t - s] : 0;
        __syncthreads();
        ss[t] += v;
        __syncthreads();
    }
    if (i < NN) {
        int off = g_poff[blockIdx.x] + ss[t] - d;
        g_off[i] = off;
        g_cur[i] = off;                       // fill cursor starts at offset
        g_rinv[i] = 1.0f / fmaxf((float)d, 1.0f);
        if (i == NN - 1) g_off[NN] = off + d;
    }
}

__global__ void k_fill(const int* __restrict__ src,
                       const int* __restrict__ dst, int E) {
    int e = blockIdx.x * blockDim.x + threadIdx.x;
    if (e >= E) return;
    int d = dst[e];
    int s = src[e];
    if (d < 0 || d >= NN || s < 0 || s >= NN) return;
    int pos = atomicAdd(&g_cur[d], 1);
    if (pos >= 0 && pos < ECAP) g_eidx[pos] = s;
}

// ---------------------------------------------------------------------------
// Tensor-core GEMM (tf32 mma.sync): C[n x 128] = A[n x 128] @ W[128 x 128]
// wmode 0: A = Ain (x, fp32),   C = g_yx (fp16);  W[k][j] = j<64 ? Wa : Wb
// wmode 1: A = g_cat (fp16),    C = Cout (fp32);  W[k][j] = k<64 ? Wa : Wb, +bias
// 8 warps 2x4, warp tile 64x32 = 4x4 m16n8k8 frags; tf32 cvt during staging.
// ---------------------------------------------------------------------------
__global__ __launch_bounds__(256, 2) void k_mm(
    const float* __restrict__ Ain,
    const float* __restrict__ Wa,
    const float* __restrict__ Wb,
    const float* __restrict__ bias,
    float* __restrict__ Cout,
    int n, int wmode)
{
    __shared__ float As[BM][36];
    __shared__ float Ws[BK][136];

    int tid  = threadIdx.x;
    int wid  = tid >> 5;
    int lane = tid & 31;
    int grp  = lane >> 2;
    int qd   = lane & 3;
    int wm   = (wid >> 2) * 64;
    int wn   = (wid & 3) * 32;
    int m0   = blockIdx.x * BM;

    float acc[4][4][4];
#pragma unroll
    for (int i = 0; i < 4; i++)
#pragma unroll
        for (int j = 0; j < 4; j++)
#pragma unroll
            for (int r = 0; r < 4; r++) acc[i][j][r] = 0.f;

    for (int kc = 0; kc < 128; kc += BK) {
        // Stage A (tf32-converted)
        if (wmode == 0) {
#pragma unroll
            for (int l = 0; l < 4; l++) {
                int f = tid + l * 256;
                int r = f >> 3;
                int c4 = f & 7;
                int row = m0 + r;
                if (row >= n) row = n - 1;
                float4 v = __ldg((const float4*)(Ain + (size_t)row * 128 + kc) + c4);
                float4 t;
                t.x = cvt_tf32(v.x); t.y = cvt_tf32(v.y);
                t.z = cvt_tf32(v.z); t.w = cvt_tf32(v.w);
                *(float4*)&As[r][c4 * 4] = t;
            }
        } else {
#pragma unroll
            for (int l = 0; l < 2; l++) {
                int f = tid + l * 256;        // 0..511
                int r = f >> 2;               // 0..127
                int c8 = f & 3;               // 8-half group within 32 k
                int row = m0 + r;
                if (row >= n) row = n - 1;
                uint4 u = *(const uint4*)(g_cat + (size_t)row * 128 + kc + c8 * 8);
                float2 f0 = __half22float2(*(__half2*)&u.x);
                float2 f1 = __half22float2(*(__half2*)&u.y);
                float2 f2 = __half22float2(*(__half2*)&u.z);
                float2 f3 = __half22float2(*(__half2*)&u.w);
                float4 t0, t1;
                t0.x = cvt_tf32(f0.x); t0.y = cvt_tf32(f0.y);
                t0.z = cvt_tf32(f1.x); t0.w = cvt_tf32(f1.y);
                t1.x = cvt_tf32(f2.x); t1.y = cvt_tf32(f2.y);
                t1.z = cvt_tf32(f3.x); t1.w = cvt_tf32(f3.y);
                *(float4*)&As[r][c8 * 8]     = t0;
                *(float4*)&As[r][c8 * 8 + 4] = t1;
            }
        }
        // Stage W (tf32-converted)
#pragma unroll
        for (int l = 0; l < 4; l++) {
            int f = tid + l * 256;
            int kk = f >> 5;
            int jc = f & 31;
            int j = jc * 4;
            int kg = kc + kk;
            float4 v;
            if (wmode == 0) {
                v = (j < 64)
                    ? __ldg((const float4*)(Wa + (size_t)kg * 64 + j))
                    : __ldg((const float4*)(Wb + (size_t)kg * 64 + (j - 64)));
            } else {
                v = (kg < 64)
                    ? __ldg((const float4*)(Wa + (size_t)kg * 128 + j))
                    : __ldg((const float4*)(Wb + (size_t)(kg - 64) * 128 + j));
            }
            float4 t;
            t.x = cvt_tf32(v.x); t.y = cvt_tf32(v.y);
            t.z = cvt_tf32(v.z); t.w = cvt_tf32(v.w);
            *(float4*)&Ws[kk][j] = t;
        }
        __syncthreads();

#pragma unroll
        for (int kk = 0; kk < BK; kk += 8) {
            uint32_t af[4][4];
#pragma unroll
            for (int mi = 0; mi < 4; mi++) {
                int m = wm + mi * 16;
                af[mi][0] = __float_as_uint(As[m + grp][kk + qd]);
                af[mi][1] = __float_as_uint(As[m + grp + 8][kk + qd]);
                af[mi][2] = __float_as_uint(As[m + grp][kk + qd + 4]);
                af[mi][3] = __float_as_uint(As[m + grp + 8][kk + qd + 4]);
            }
            uint32_t bf[4][2];
#pragma unroll
            for (int ni = 0; ni < 4; ni++) {
                int nn = wn + ni * 8 + grp;
                bf[ni][0] = __float_as_uint(Ws[kk + qd][nn]);
                bf[ni][1] = __float_as_uint(Ws[kk + qd + 4][nn]);
            }
#pragma unroll
            for (int mi = 0; mi < 4; mi++)
#pragma unroll
                for (int ni = 0; ni < 4; ni++)
                    mma_tf32(acc[mi][ni], af[mi], bf[ni]);
        }
        __syncthreads();
    }

    // Epilogue
    if (wmode == 0) {
#pragma unroll
        for (int mi = 0; mi < 4; mi++) {
            int r0 = m0 + wm + mi * 16 + grp;
            int r1 = r0 + 8;
#pragma unroll
            for (int ni = 0; ni < 4; ni++) {
                int c = wn + ni * 8 + qd * 2;
                if (r0 < n)
                    *(__half2*)(g_yx + (size_t)r0 * 128 + c) =
                        __floats2half2_rn(acc[mi][ni][0], acc[mi][ni][1]);
                if (r1 < n)
                    *(__half2*)(g_yx + (size_t)r1 * 128 + c) =
                        __floats2half2_rn(acc[mi][ni][2], acc[mi][ni][3]);
            }
        }
    } else {
        float bb[4][2];
#pragma unroll
        for (int ni = 0; ni < 4; ni++) {
            int c = wn + ni * 8 + qd * 2;
            bb[ni][0] = __ldg(bias + c);
            bb[ni][1] = __ldg(bias + c + 1);
        }
#pragma unroll
        for (int mi = 0; mi < 4; mi++) {
            int r0 = m0 + wm + mi * 16 + grp;
            int r1 = r0 + 8;
#pragma unroll
            for (int ni = 0; ni < 4; ni++) {
                int c = wn + ni * 8 + qd * 2;
                if (r0 < n)
                    *(float2*)(Cout + (size_t)r0 * 128 + c) =
                        make_float2(acc[mi][ni][0] + bb[ni][0],
                                    acc[mi][ni][1] + bb[ni][1]);
                if (r1 < n)
                    *(float2*)(Cout + (size_t)r1 * 128 + c) =
                        make_float2(acc[mi][ni][2] + bb[ni][0],
                                    acc[mi][ni][3] + bb[ni][1]);
            }
        }
    }
}

// ---------------------------------------------------------------------------
// Gather-side aggregation over fp16 features, fp32 accumulation.
// 16 lanes x 8B (4 halves) cover a 64-col row; half-warps own even/odd slots.
// layer 0: h  = relu(mean(y1[nbrs]) + b1 + xr)  -> g_cat[64:]
// layer 1: mh = mean(h[nbrs])                   -> g_cat[0:64]
// ---------------------------------------------------------------------------
__global__ __launch_bounds__(256) void k_agg(const float* __restrict__ b1,
                                             int layer)
{
    int node = blockIdx.x * 8 + (threadIdx.x >> 5);
    if (node >= NN) return;
    int lane = threadIdx.x & 31;
    int q    = lane & 15;     // 4-half slot (cols 4q..4q+3)
    int hs   = lane >> 4;     // edge stream

    const __half* val = (layer == 0) ? g_yx : (g_cat + 64);
    int beg = g_off[node];
    int end = g_off[node + 1];

    float4 A = {0.f, 0.f, 0.f, 0.f};
    float4 B = {0.f, 0.f, 0.f, 0.f};
    int e = beg + hs;
    for (; e + 2 < end; e += 4) {
        int s0 = __ldg(&g_eidx[e]);
        int s1 = __ldg(&g_eidx[e + 2]);
        uint2 u0 = *(const uint2*)(val + (size_t)s0 * 128 + q * 4);
        uint2 u1 = *(const uint2*)(val + (size_t)s1 * 128 + q * 4);
        float2 a0 = __half22float2(*(__half2*)&u0.x);
        float2 a1 = __half22float2(*(__half2*)&u0.y);
        float2 c0 = __half22float2(*(__half2*)&u1.x);
        float2 c1 = __half22float2(*(__half2*)&u1.y);
        A.x += a0.x; A.y += a0.y; A.z += a1.x; A.w += a1.y;
        B.x += c0.x; B.y += c0.y; B.z += c1.x; B.w += c1.y;
    }
    if (e < end) {
        int s = __ldg(&g_eidx[e]);
        uint2 u = *(const uint2*)(val + (size_t)s * 128 + q * 4);
        float2 a0 = __half22float2(*(__half2*)&u.x);
        float2 a1 = __half22float2(*(__half2*)&u.y);
        A.x += a0.x; A.y += a0.y; A.z += a1.x; A.w += a1.y;
    }
    float4 acc;
    acc.x = A.x + B.x; acc.y = A.y + B.y; acc.z = A.z + B.z; acc.w = A.w + B.w;
    acc.x += __shfl_xor_sync(0xffffffffu, acc.x, 16);
    acc.y += __shfl_xor_sync(0xffffffffu, acc.y, 16);
    acc.z += __shfl_xor_sync(0xffffffffu, acc.z, 16);
    acc.w += __shfl_xor_sync(0xffffffffu, acc.w, 16);

    if (hs == 0) {
        float r = g_rinv[node];
        if (layer == 0) {
            uint2 ux = *(const uint2*)(g_yx + (size_t)node * 128 + 64 + q * 4);
            float2 x0 = __half22float2(*(__half2*)&ux.x);
            float2 x1 = __half22float2(*(__half2*)&ux.y);
            float4 bb = __ldg((const float4*)b1 + q);
            float h0 = fmaxf(fmaf(acc.x, r, bb.x + x0.x), 0.f);
            float h1 = fmaxf(fmaf(acc.y, r, bb.y + x0.y), 0.f);
            float h2 = fmaxf(fmaf(acc.z, r, bb.z + x1.x), 0.f);
            float h3 = fmaxf(fmaf(acc.w, r, bb.w + x1.y), 0.f);
            uint2 st;
            *(__half2*)&st.x = __floats2half2_rn(h0, h1);
            *(__half2*)&st.y = __floats2half2_rn(h2, h3);
            *(uint2*)(g_cat + (size_t)node * 128 + 64 + q * 4) = st;
        } else {
            uint2 st;
            *(__half2*)&st.x = __floats2half2_rn(acc.x * r, acc.y * r);
            *(__half2*)&st.y = __floats2half2_rn(acc.z * r, acc.w * r);
            *(uint2*)(g_cat + (size_t)node * 128 + q * 4) = st;
        }
    }
}

// ---------------------------------------------------------------------------
extern "C" void kernel_launch(void* const* d_in, const int* in_sizes, int n_in,
                              void* d_out, int out_size) {
    const float* x   = (const float*)d_in[0];
    const int*   ei  = (const int*)d_in[1];     // int32 edge_index [2, E]
    const float* w1l = (const float*)d_in[2];
    const float* b1  = (const float*)d_in[3];
    const float* w1r = (const float*)d_in[4];
    const float* w2l = (const float*)d_in[5];
    const float* b2  = (const float*)d_in[6];
    const float* w2r = (const float*)d_in[7];
    float* out = (float*)d_out;

    int E = in_sizes[1] / 2;
    const int* src = ei;
    const int* dst = ei + E;

    int mgrid = (NN + BM - 1) / BM;   // 782

    k_init<<<(NN + 511) / 512, 512>>>();
    k_deg <<<(E + 255) / 256, 256>>>(dst, E);
    k_scan_part<<<NPART, SCAN_B>>>();
    // Layer-1 GEMM as launch #4 (independent of CSR; lands in profiler window)
    k_mm<<<mgrid, 256>>>(x, w1l, w1r, nullptr, nullptr, NN, 0);
    k_scan_top <<<1, 512>>>();
    k_scan_off <<<NPART, SCAN_B>>>();
    k_fill<<<(E + 255) / 256, 256>>>(src, dst, E);

    k_agg<<<(NN + 7) / 8, 256>>>(b1, 0);
    k_agg<<<(NN + 7) / 8, 256>>>(b1, 1);

    // Layer-2 GEMM (+bias) straight to output
    k_mm<<<mgrid, 256>>>(nullptr /*A=g_cat via wmode*/, w2l, w2r, b2, out, NN, 1);
}

// round 14
// speedup vs baseline: 5.1273x; 1.0550x over previous
#include <cuda_runtime.h>
#include <cuda_fp16.h>
#include <cstdint>
#include <cstddef>

#define NN    100000
#define IND   128
#define HID   64
#define OUTD  128
#define ECAP  1700000
#define SCAN_B 256
#define NPART ((NN + SCAN_B - 1) / SCAN_B)   // 391

#define BM 128
#define BK 64
#define KPAD 72     // stride in halves; (36*r + qd) % 32 hits all banks

// Scratch (device globals — no allocation allowed). Node features in fp16.
__device__ __align__(16) __half g_yx [(size_t)NN * 128]; // 0-63: y1=x@w1l, 64-127: xr=x@w1r
__device__ __align__(16) __half g_cat[(size_t)NN * 128]; // 0-63: mh, 64-127: h
__device__ __align__(16) float g_rinv[NN];
__device__ __align__(16) int   g_deg[NN];
__device__ int   g_cur[NN];
__device__ int   g_off[NN + 1];
__device__ int   g_part[NPART];
__device__ int   g_poff[NPART];
__device__ int   g_eidx[ECAP];

// ---------------------------------------------------------------------------
__device__ __forceinline__ void mma_f16(float* d, const uint32_t* a,
                                        const uint32_t* b) {
    asm("mma.sync.aligned.m16n8k16.row.col.f32.f16.f16.f32 "
        "{%0,%1,%2,%3}, {%4,%5,%6,%7}, {%8,%9}, {%0,%1,%2,%3};"
        : "+f"(d[0]), "+f"(d[1]), "+f"(d[2]), "+f"(d[3])
        : "r"(a[0]), "r"(a[1]), "r"(a[2]), "r"(a[3]),
          "r"(b[0]), "r"(b[1]));
}

// ---------------------------------------------------------------------------
__global__ void k_init() {
    int i = blockIdx.x * blockDim.x + threadIdx.x;
    if (i < NN) g_deg[i] = 0;
}

__global__ void k_deg(const int* __restrict__ dst, int E) {
    int e = blockIdx.x * blockDim.x + threadIdx.x;
    if (e < E) {
        int d = dst[e];
        if (d >= 0 && d < NN) atomicAdd(&g_deg[d], 1);
    }
}

// ---------------------------------------------------------------------------
// Multi-block scan (3 phases)
// ---------------------------------------------------------------------------
__global__ __launch_bounds__(SCAN_B) void k_scan_part() {
    __shared__ int sred[SCAN_B];
    int t = threadIdx.x;
    int i = blockIdx.x * SCAN_B + t;
    sred[t] = (i < NN) ? g_deg[i] : 0;
    __syncthreads();
#pragma unroll
    for (int s = SCAN_B / 2; s > 0; s >>= 1) {
        if (t < s) sred[t] += sred[t + s];
        __syncthreads();
    }
    if (t == 0) g_part[blockIdx.x] = sred[0];
}

__global__ __launch_bounds__(512) void k_scan_top() {
    __shared__ int ss[512];
    int t = threadIdx.x;
    ss[t] = (t < NPART) ? g_part[t] : 0;
    __syncthreads();
#pragma unroll
    for (int d = 1; d < 512; d <<= 1) {
        int v = (t >= d) ? ss[t - d] : 0;
        __syncthreads();
        ss[t] += v;
        __syncthreads();
    }
    if (t < NPART) g_poff[t] = (t == 0) ? 0 : ss[t - 1];
}

__global__ __launch_bounds__(SCAN_B) void k_scan_off() {
    __shared__ int ss[SCAN_B];
    int t = threadIdx.x;
    int i = blockIdx.x * SCAN_B + t;
    int d = (i < NN) ? g_deg[i] : 0;
    ss[t] = d;
    __syncthreads();
#pragma unroll
    for (int s = 1; s < SCAN_B; s <<= 1) {
        int v = (t >= s) ? ss[t - s] : 0;
        __syncthreads();
        ss[t] += v;
        __syncthreads();
    }
    if (i < NN) {
        int off = g_poff[blockIdx.x] + ss[t] - d;
        g_off[i] = off;
        g_cur[i] = off;
        g_rinv[i] = 1.0f / fmaxf((float)d, 1.0f);
        if (i == NN - 1) g_off[NN] = off + d;
    }
}

__global__ void k_fill(const int* __restrict__ src,
                       const int* __restrict__ dst, int E) {
    int e = blockIdx.x * blockDim.x + threadIdx.x;
    if (e >= E) return;
    int d = dst[e];
    int s = src[e];
    if (d < 0 || d >= NN || s < 0 || s >= NN) return;
    int pos = atomicAdd(&g_cur[d], 1);
    if (pos >= 0 && pos < ECAP) g_eidx[pos] = s;
}

// ---------------------------------------------------------------------------
// fp16 tensor-core GEMM (mma.m16n8k16): C[n x 128] = A[n x 128] @ W[128 x 128]
// BM=128, BK=64 (2 chunks), 8 warps 2x4, warp tile 64x32 = 4x4x(k16) frags.
// As[m][k] halves stride 72; Ws[n][k] halves stride 72 (W transposed during
// staging so B fragments are contiguous-in-k uint32 LDS, conflict-free).
// wmode 0: A = Ain (x fp32),  C = g_yx (fp16)
// wmode 1: A = g_cat (fp16),  C = Cout (fp32) + bias
// ---------------------------------------------------------------------------
__global__ __launch_bounds__(256, 2) void k_mm(
    const float* __restrict__ Ain,
    const float* __restrict__ Wa,
    const float* __restrict__ Wb,
    const float* __restrict__ bias,
    float* __restrict__ Cout,
    int n, int wmode)
{
    __shared__ __half As[BM][KPAD];    // 128 x 72 x 2B = 18.4 KB
    __shared__ __half Ws[128][KPAD];   // [n][k]        = 18.4 KB

    int tid  = threadIdx.x;
    int wid  = tid >> 5;
    int lane = tid & 31;
    int grp  = lane >> 2;              // 0..7
    int qd   = lane & 3;               // 0..3
    int wm   = (wid >> 2) * 64;
    int wn   = (wid & 3) * 32;
    int m0   = blockIdx.x * BM;

    float acc[4][4][4];
#pragma unroll
    for (int i = 0; i < 4; i++)
#pragma unroll
        for (int j = 0; j < 4; j++)
#pragma unroll
            for (int r = 0; r < 4; r++) acc[i][j][r] = 0.f;

    for (int kc = 0; kc < 128; kc += BK) {
        // ---- Stage A: 128 rows x 64 k (halves) ----
        if (wmode == 0) {
#pragma unroll
            for (int l = 0; l < 4; l++) {
                int f = tid + l * 256;         // 0..1023
                int r = f >> 3;                // 0..127
                int c8 = f & 7;                // 8-half group
                int row = m0 + r;
                if (row >= n) row = n - 1;
                const float4* p = (const float4*)(Ain + (size_t)row * 128 + kc + c8 * 8);
                float4 v0 = __ldg(p);
                float4 v1 = __ldg(p + 1);
                uint4 st;
                *(__half2*)&st.x = __floats2half2_rn(v0.x, v0.y);
                *(__half2*)&st.y = __floats2half2_rn(v0.z, v0.w);
                *(__half2*)&st.z = __floats2half2_rn(v1.x, v1.y);
                *(__half2*)&st.w = __floats2half2_rn(v1.z, v1.w);
                *(uint4*)&As[r][c8 * 8] = st;
            }
        } else {
#pragma unroll
            for (int l = 0; l < 4; l++) {
                int f = tid + l * 256;
                int r = f >> 3;
                int c8 = f & 7;
                int row = m0 + r;
                if (row >= n) row = n - 1;
                uint4 u = *(const uint4*)(g_cat + (size_t)row * 128 + kc + c8 * 8);
                *(uint4*)&As[r][c8 * 8] = u;
            }
        }
        // ---- Stage W transposed: Ws[n][k], 128 n x 64 k ----
#pragma unroll
        for (int l = 0; l < 4; l++) {
            int f = tid + l * 256;             // 0..1023
            int nidx = f >> 3;                 // 0..127
            int kq = f & 7;                    // 8-k group
            __half tmp[8];
#pragma unroll
            for (int i = 0; i < 8; i++) {
                int kg = kc + kq * 8 + i;
                float v;
                if (wmode == 0) {
                    v = (nidx < 64)
                        ? __ldg(Wa + (size_t)kg * 64 + nidx)
                        : __ldg(Wb + (size_t)kg * 64 + (nidx - 64));
                } else {
                    v = (kg < 64)
                        ? __ldg(Wa + (size_t)kg * 128 + nidx)
                        : __ldg(Wb + (size_t)(kg - 64) * 128 + nidx);
                }
                tmp[i] = __float2half_rn(v);
            }
            *(uint4*)&Ws[nidx][kq * 8] = *(uint4*)tmp;
        }
        __syncthreads();

        // ---- Mainloop: 4 k16-steps per chunk ----
#pragma unroll
        for (int kk = 0; kk < BK; kk += 16) {
            uint32_t af[4][4];
#pragma unroll
            for (int mi = 0; mi < 4; mi++) {
                int mt = wm + mi * 16;
                af[mi][0] = *(const uint32_t*)&As[mt + grp][kk + 2 * qd];
                af[mi][1] = *(const uint32_t*)&As[mt + grp + 8][kk + 2 * qd];
                af[mi][2] = *(const uint32_t*)&As[mt + grp][kk + 2 * qd + 8];
                af[mi][3] = *(const uint32_t*)&As[mt + grp + 8][kk + 2 * qd + 8];
            }
            uint32_t bf[4][2];
#pragma unroll
            for (int ni = 0; ni < 4; ni++) {
                int nn = wn + ni * 8 + grp;
                bf[ni][0] = *(const uint32_t*)&Ws[nn][kk + 2 * qd];
                bf[ni][1] = *(const uint32_t*)&Ws[nn][kk + 2 * qd + 8];
            }
#pragma unroll
            for (int mi = 0; mi < 4; mi++)
#pragma unroll
                for (int ni = 0; ni < 4; ni++)
                    mma_f16(acc[mi][ni], af[mi], bf[ni]);
        }
        __syncthreads();
    }

    // ---- Epilogue ----
    if (wmode == 0) {
#pragma unroll
        for (int mi = 0; mi < 4; mi++) {
            int r0 = m0 + wm + mi * 16 + grp;
            int r1 = r0 + 8;
#pragma unroll
            for (int ni = 0; ni < 4; ni++) {
                int c = wn + ni * 8 + qd * 2;
                if (r0 < n)
                    *(__half2*)(g_yx + (size_t)r0 * 128 + c) =
                        __floats2half2_rn(acc[mi][ni][0], acc[mi][ni][1]);
                if (r1 < n)
                    *(__half2*)(g_yx + (size_t)r1 * 128 + c) =
                        __floats2half2_rn(acc[mi][ni][2], acc[mi][ni][3]);
            }
        }
    } else {
        float bb[4][2];
#pragma unroll
        for (int ni = 0; ni < 4; ni++) {
            int c = wn + ni * 8 + qd * 2;
            bb[ni][0] = __ldg(bias + c);
            bb[ni][1] = __ldg(bias + c + 1);
        }
#pragma unroll
        for (int mi = 0; mi < 4; mi++) {
            int r0 = m0 + wm + mi * 16 + grp;
            int r1 = r0 + 8;
#pragma unroll
            for (int ni = 0; ni < 4; ni++) {
                int c = wn + ni * 8 + qd * 2;
                if (r0 < n)
                    *(float2*)(Cout + (size_t)r0 * 128 + c) =
                        make_float2(acc[mi][ni][0] + bb[ni][0],
                                    acc[mi][ni][1] + bb[ni][1]);
                if (r1 < n)
                    *(float2*)(Cout + (size_t)r1 * 128 + c) =
                        make_float2(acc[mi][ni][2] + bb[ni][0],
                                    acc[mi][ni][3] + bb[ni][1]);
            }
        }
    }
}

// ---------------------------------------------------------------------------
// Gather-side aggregation over fp16 features, fp32 accumulation.
// layer 0: h  = relu(mean(y1[nbrs]) + b1 + xr)  -> g_cat[64:]
// layer 1: mh = mean(h[nbrs])                   -> g_cat[0:64]
// ---------------------------------------------------------------------------
__global__ __launch_bounds__(256) void k_agg(const float* __restrict__ b1,
                                             int layer)
{
    int node = blockIdx.x * 8 + (threadIdx.x >> 5);
    if (node >= NN) return;
    int lane = threadIdx.x & 31;
    int q    = lane & 15;
    int hs   = lane >> 4;

    const __half* val = (layer == 0) ? g_yx : (g_cat + 64);
    int beg = g_off[node];
    int end = g_off[node + 1];

    float4 A = {0.f, 0.f, 0.f, 0.f};
    float4 B = {0.f, 0.f, 0.f, 0.f};
    int e = beg + hs;
    for (; e + 2 < end; e += 4) {
        int s0 = __ldg(&g_eidx[e]);
        int s1 = __ldg(&g_eidx[e + 2]);
        uint2 u0 = *(const uint2*)(val + (size_t)s0 * 128 + q * 4);
        uint2 u1 = *(const uint2*)(val + (size_t)s1 * 128 + q * 4);
        float2 a0 = __half22float2(*(__half2*)&u0.x);
        float2 a1 = __half22float2(*(__half2*)&u0.y);
        float2 c0 = __half22float2(*(__half2*)&u1.x);
        float2 c1 = __half22float2(*(__half2*)&u1.y);
        A.x += a0.x; A.y += a0.y; A.z += a1.x; A.w += a1.y;
        B.x += c0.x; B.y += c0.y; B.z += c1.x; B.w += c1.y;
    }
    if (e < end) {
        int s = __ldg(&g_eidx[e]);
        uint2 u = *(const uint2*)(val + (size_t)s * 128 + q * 4);
        float2 a0 = __half22float2(*(__half2*)&u.x);
        float2 a1 = __half22float2(*(__half2*)&u.y);
        A.x += a0.x; A.y += a0.y; A.z += a1.x; A.w += a1.y;
    }
    float4 acc;
    acc.x = A.x + B.x; acc.y = A.y + B.y; acc.z = A.z + B.z; acc.w = A.w + B.w;
    acc.x += __shfl_xor_sync(0xffffffffu, acc.x, 16);
    acc.y += __shfl_xor_sync(0xffffffffu, acc.y, 16);
    acc.z += __shfl_xor_sync(0xffffffffu, acc.z, 16);
    acc.w += __shfl_xor_sync(0xffffffffu, acc.w, 16);

    if (hs == 0) {
        float r = g_rinv[node];
        if (layer == 0) {
            uint2 ux = *(const uint2*)(g_yx + (size_t)node * 128 + 64 + q * 4);
            float2 x0 = __half22float2(*(__half2*)&ux.x);
            float2 x1 = __half22float2(*(__half2*)&ux.y);
            float4 bb = __ldg((const float4*)b1 + q);
            float h0 = fmaxf(fmaf(acc.x, r, bb.x + x0.x), 0.f);
            float h1 = fmaxf(fmaf(acc.y, r, bb.y + x0.y), 0.f);
            float h2 = fmaxf(fmaf(acc.z, r, bb.z + x1.x), 0.f);
            float h3 = fmaxf(fmaf(acc.w, r, bb.w + x1.y), 0.f);
            uint2 st;
            *(__half2*)&st.x = __floats2half2_rn(h0, h1);
            *(__half2*)&st.y = __floats2half2_rn(h2, h3);
            *(uint2*)(g_cat + (size_t)node * 128 + 64 + q * 4) = st;
        } else {
            uint2 st;
            *(__half2*)&st.x = __floats2half2_rn(acc.x * r, acc.y * r);
            *(__half2*)&st.y = __floats2half2_rn(acc.z * r, acc.w * r);
            *(uint2*)(g_cat + (size_t)node * 128 + q * 4) = st;
        }
    }
}

// ---------------------------------------------------------------------------
extern "C" void kernel_launch(void* const* d_in, const int* in_sizes, int n_in,
                              void* d_out, int out_size) {
    const float* x   = (const float*)d_in[0];
    const int*   ei  = (const int*)d_in[1];     // int32 edge_index [2, E]
    const float* w1l = (const float*)d_in[2];
    const float* b1  = (const float*)d_in[3];
    const float* w1r = (const float*)d_in[4];
    const float* w2l = (const float*)d_in[5];
    const float* b2  = (const float*)d_in[6];
    const float* w2r = (const float*)d_in[7];
    float* out = (float*)d_out;

    int E = in_sizes[1] / 2;
    const int* src = ei;
    const int* dst = ei + E;

    int mgrid = (NN + BM - 1) / BM;   // 782

    k_init<<<(NN + 511) / 512, 512>>>();
    k_deg <<<(E + 255) / 256, 256>>>(dst, E);
    k_scan_part<<<NPART, SCAN_B>>>();
    // Layer-1 GEMM as launch #4 (independent of CSR; lands in profiler window)
    k_mm<<<mgrid, 256>>>(x, w1l, w1r, nullptr, nullptr, NN, 0);
    k_scan_top <<<1, 512>>>();
    k_scan_off <<<NPART, SCAN_B>>>();
    k_fill<<<(E + 255) / 256, 256>>>(src, dst, E);

    k_agg<<<(NN + 7) / 8, 256>>>(b1, 0);
    k_agg<<<(NN + 7) / 8, 256>>>(b1, 1);

    // Layer-2 GEMM (+bias) straight to output
    k_mm<<<mgrid, 256>>>(nullptr /*A=g_cat via wmode*/, w2l, w2r, b2, out, NN, 1);
}

// round 15
// speedup vs baseline: 6.2771x; 1.2243x over previous
#include <cuda_runtime.h>
#include <cuda_fp16.h>
#include <cstdint>
#include <cstddef>

#define NN    100000
#define IND   128
#define HID   64
#define OUTD  128
#define ECAP  1700000
#define SCAN_B 256
#define NPART ((NN + SCAN_B - 1) / SCAN_B)   // 391

#define BM 128
#define KPAD 136    // stride in halves; bank = (4*row + qd) % 32 -> conflict-free
#define MM_SMEM (2 * 128 * KPAD * (int)sizeof(__half))   // 69632 B

// Scratch (device globals — no allocation allowed). Node features in fp16.
__device__ __align__(16) __half g_yx [(size_t)NN * 128]; // 0-63: y1, 64-127: xr
__device__ __align__(16) __half g_cat[(size_t)NN * 128]; // 0-63: mh, 64-127: h
__device__ __align__(16) __half g_wt[2][128][128];       // fp16 W, [layer][n][k]
__device__ __align__(16) float g_rinv[NN];
__device__ __align__(16) int   g_deg[NN];
__device__ int   g_cur[NN];
__device__ int   g_off[NN + 1];
__device__ int   g_part[NPART];
__device__ int   g_poff[NPART];
__device__ int   g_eidx[ECAP];

// ---------------------------------------------------------------------------
__device__ __forceinline__ void mma_f16(float* d, const uint32_t* a,
                                        const uint32_t* b) {
    asm("mma.sync.aligned.m16n8k16.row.col.f32.f16.f16.f32 "
        "{%0,%1,%2,%3}, {%4,%5,%6,%7}, {%8,%9}, {%0,%1,%2,%3};"
        : "+f"(d[0]), "+f"(d[1]), "+f"(d[2]), "+f"(d[3])
        : "r"(a[0]), "r"(a[1]), "r"(a[2]), "r"(a[3]),
          "r"(b[0]), "r"(b[1]));
}

// ---------------------------------------------------------------------------
__global__ void k_init() {
    int i = blockIdx.x * blockDim.x + threadIdx.x;
    if (i < NN) g_deg[i] = 0;
}

__global__ void k_deg(const int* __restrict__ dst, int E) {
    int e = blockIdx.x * blockDim.x + threadIdx.x;
    if (e < E) {
        int d = dst[e];
        if (d >= 0 && d < NN) atomicAdd(&g_deg[d], 1);
    }
}

// ---------------------------------------------------------------------------
// One-time W convert/transpose to fp16 [n][k] (both layers).
// ---------------------------------------------------------------------------
__global__ __launch_bounds__(256) void k_prepw(
    const float* __restrict__ w1l, const float* __restrict__ w1r,
    const float* __restrict__ w2l, const float* __restrict__ w2r)
{
    int idx = blockIdx.x * blockDim.x + threadIdx.x;   // 0..32767
    if (idx >= 2 * 128 * 128) return;
    int which = idx >> 14;
    int r = (idx >> 7) & 127;   // n
    int c = idx & 127;          // k
    float v;
    if (which == 0)
        v = (r < 64) ? w1l[(size_t)c * 64 + r] : w1r[(size_t)c * 64 + (r - 64)];
    else
        v = (c < 64) ? w2l[(size_t)c * 128 + r] : w2r[(size_t)(c - 64) * 128 + r];
    g_wt[which][r][c] = __float2half_rn(v);
}

// ---------------------------------------------------------------------------
// Multi-block scan (3 phases)
// ---------------------------------------------------------------------------
__global__ __launch_bounds__(SCAN_B) void k_scan_part() {
    __shared__ int sred[SCAN_B];
    int t = threadIdx.x;
    int i = blockIdx.x * SCAN_B + t;
    sred[t] = (i < NN) ? g_deg[i] : 0;
    __syncthreads();
#pragma unroll
    for (int s = SCAN_B / 2; s > 0; s >>= 1) {
        if (t < s) sred[t] += sred[t + s];
        __syncthreads();
    }
    if (t == 0) g_part[blockIdx.x] = sred[0];
}

__global__ __launch_bounds__(512) void k_scan_top() {
    __shared__ int ss[512];
    int t = threadIdx.x;
    ss[t] = (t < NPART) ? g_part[t] : 0;
    __syncthreads();
#pragma unroll
    for (int d = 1; d < 512; d <<= 1) {
        int v = (t >= d) ? ss[t - d] : 0;
        __syncthreads();
        ss[t] += v;
        __syncthreads();
    }
    if (t < NPART) g_poff[t] = (t == 0) ? 0 : ss[t - 1];
}

__global__ __launch_bounds__(SCAN_B) void k_scan_off() {
    __shared__ int ss[SCAN_B];
    int t = threadIdx.x;
    int i = blockIdx.x * SCAN_B + t;
    int d = (i < NN) ? g_deg[i] : 0;
    ss[t] = d;
    __syncthreads();
#pragma unroll
    for (int s = 1; s < SCAN_B; s <<= 1) {
        int v = (t >= s) ? ss[t - s] : 0;
        __syncthreads();
        ss[t] += v;
        __syncthreads();
    }
    if (i < NN) {
        int off = g_poff[blockIdx.x] + ss[t] - d;
        g_off[i] = off;
        g_cur[i] = off;
        g_rinv[i] = 1.0f / fmaxf((float)d, 1.0f);
        if (i == NN - 1) g_off[NN] = off + d;
    }
}

__global__ void k_fill(const int* __restrict__ src,
                       const int* __restrict__ dst, int E) {
    int e = blockIdx.x * blockDim.x + threadIdx.x;
    if (e >= E) return;
    int d = dst[e];
    int s = src[e];
    if (d < 0 || d >= NN || s < 0 || s >= NN) return;
    int pos = atomicAdd(&g_cur[d], 1);
    if (pos >= 0 && pos < ECAP) g_eidx[pos] = s;
}

// ---------------------------------------------------------------------------
// fp16 tensor-core GEMM, single-stage full-K (BK=128):
//   C[n x 128] = A[n x 128] @ W[128 x 128]
// W pre-converted fp16 [n][k] in g_wt -> staging is coalesced uint4 copies.
// Dynamic smem: As[128][136] + Ws[128][136] halves = 69.6 KB.
// wmode 0: A = Ain (x fp32),  C = g_yx (fp16)
// wmode 1: A = g_cat (fp16),  C = Cout (fp32) + bias
// ---------------------------------------------------------------------------
__global__ __launch_bounds__(256, 2) void k_mm(
    const float* __restrict__ Ain,
    const float* __restrict__ bias,
    float* __restrict__ Cout,
    int n, int wmode)
{
    extern __shared__ __half smem[];
    __half* As = smem;                  // [128][KPAD]
    __half* Ws = smem + 128 * KPAD;     // [128][KPAD]

    int tid  = threadIdx.x;
    int wid  = tid >> 5;
    int lane = tid & 31;
    int grp  = lane >> 2;
    int qd   = lane & 3;
    int wm   = (wid >> 2) * 64;
    int wn   = (wid & 3) * 32;
    int m0   = blockIdx.x * BM;

    // ---- Stage A: 128 rows x 128 k halves ----
    if (wmode == 0) {
#pragma unroll
        for (int l = 0; l < 8; l++) {
            int f = tid + l * 256;          // 0..2047
            int r = f >> 4;                 // 0..127
            int c8 = f & 15;                // 8-half group
            int row = m0 + r;
            if (row >= n) row = n - 1;
            const float4* p = (const float4*)(Ain + (size_t)row * 128 + c8 * 8);
            float4 v0 = __ldg(p);
            float4 v1 = __ldg(p + 1);
            uint4 st;
            *(__half2*)&st.x = __floats2half2_rn(v0.x, v0.y);
            *(__half2*)&st.y = __floats2half2_rn(v0.z, v0.w);
            *(__half2*)&st.z = __floats2half2_rn(v1.x, v1.y);
            *(__half2*)&st.w = __floats2half2_rn(v1.z, v1.w);
            *(uint4*)&As[r * KPAD + c8 * 8] = st;
        }
    } else {
#pragma unroll
        for (int l = 0; l < 8; l++) {
            int f = tid + l * 256;
            int r = f >> 4;
            int c8 = f & 15;
            int row = m0 + r;
            if (row >= n) row = n - 1;
            uint4 u = *(const uint4*)(g_cat + (size_t)row * 128 + c8 * 8);
            *(uint4*)&As[r * KPAD + c8 * 8] = u;
        }
    }
    // ---- Stage W: coalesced uint4 copies from pre-converted g_wt ----
    {
        const __half* wsrc = &g_wt[wmode][0][0];
#pragma unroll
        for (int l = 0; l < 8; l++) {
            int f = tid + l * 256;          // 0..2047
            int nidx = f >> 4;              // 0..127
            int kq = f & 15;                // 8-half group
            uint4 u = *(const uint4*)(wsrc + (size_t)nidx * 128 + kq * 8);
            *(uint4*)&Ws[nidx * KPAD + kq * 8] = u;
        }
    }
    __syncthreads();

    float acc[4][4][4];
#pragma unroll
    for (int i = 0; i < 4; i++)
#pragma unroll
        for (int j = 0; j < 4; j++)
#pragma unroll
            for (int r = 0; r < 4; r++) acc[i][j][r] = 0.f;

    // ---- Mainloop: 8 k16-steps ----
#pragma unroll
    for (int kk = 0; kk < 128; kk += 16) {
        uint32_t af[4][4];
#pragma unroll
        for (int mi = 0; mi < 4; mi++) {
            int mt = wm + mi * 16;
            af[mi][0] = *(const uint32_t*)&As[(mt + grp) * KPAD + kk + 2 * qd];
            af[mi][1] = *(const uint32_t*)&As[(mt + grp + 8) * KPAD + kk + 2 * qd];
            af[mi][2] = *(const uint32_t*)&As[(mt + grp) * KPAD + kk + 2 * qd + 8];
            af[mi][3] = *(const uint32_t*)&As[(mt + grp + 8) * KPAD + kk + 2 * qd + 8];
        }
        uint32_t bf[4][2];
#pragma unroll
        for (int ni = 0; ni < 4; ni++) {
            int nn = wn + ni * 8 + grp;
            bf[ni][0] = *(const uint32_t*)&Ws[nn * KPAD + kk + 2 * qd];
            bf[ni][1] = *(const uint32_t*)&Ws[nn * KPAD + kk + 2 * qd + 8];
        }
#pragma unroll
        for (int mi = 0; mi < 4; mi++)
#pragma unroll
            for (int ni = 0; ni < 4; ni++)
                mma_f16(acc[mi][ni], af[mi], bf[ni]);
    }

    // ---- Epilogue ----
    if (wmode == 0) {
#pragma unroll
        for (int mi = 0; mi < 4; mi++) {
            int r0 = m0 + wm + mi * 16 + grp;
            int r1 = r0 + 8;
#pragma unroll
            for (int ni = 0; ni < 4; ni++) {
                int c = wn + ni * 8 + qd * 2;
                if (r0 < n)
                    *(__half2*)(g_yx + (size_t)r0 * 128 + c) =
                        __floats2half2_rn(acc[mi][ni][0], acc[mi][ni][1]);
                if (r1 < n)
                    *(__half2*)(g_yx + (size_t)r1 * 128 + c) =
                        __floats2half2_rn(acc[mi][ni][2], acc[mi][ni][3]);
            }
        }
    } else {
        float bb[4][2];
#pragma unroll
        for (int ni = 0; ni < 4; ni++) {
            int c = wn + ni * 8 + qd * 2;
            bb[ni][0] = __ldg(bias + c);
            bb[ni][1] = __ldg(bias + c + 1);
        }
#pragma unroll
        for (int mi = 0; mi < 4; mi++) {
            int r0 = m0 + wm + mi * 16 + grp;
            int r1 = r0 + 8;
#pragma unroll
            for (int ni = 0; ni < 4; ni++) {
                int c = wn + ni * 8 + qd * 2;
                if (r0 < n)
                    *(float2*)(Cout + (size_t)r0 * 128 + c) =
                        make_float2(acc[mi][ni][0] + bb[ni][0],
                                    acc[mi][ni][1] + bb[ni][1]);
                if (r1 < n)
                    *(float2*)(Cout + (size_t)r1 * 128 + c) =
                        make_float2(acc[mi][ni][2] + bb[ni][0],
                                    acc[mi][ni][3] + bb[ni][1]);
            }
        }
    }
}

// ---------------------------------------------------------------------------
// Gather-side aggregation over fp16 features, fp32 accumulation.
// ---------------------------------------------------------------------------
__global__ __launch_bounds__(256) void k_agg(const float* __restrict__ b1,
                                             int layer)
{
    int node = blockIdx.x * 8 + (threadIdx.x >> 5);
    if (node >= NN) return;
    int lane = threadIdx.x & 31;
    int q    = lane & 15;
    int hs   = lane >> 4;

    const __half* val = (layer == 0) ? g_yx : (g_cat + 64);
    int beg = g_off[node];
    int end = g_off[node + 1];

    float4 A = {0.f, 0.f, 0.f, 0.f};
    float4 B = {0.f, 0.f, 0.f, 0.f};
    int e = beg + hs;
    for (; e + 2 < end; e += 4) {
        int s0 = __ldg(&g_eidx[e]);
        int s1 = __ldg(&g_eidx[e + 2]);
        uint2 u0 = *(const uint2*)(val + (size_t)s0 * 128 + q * 4);
        uint2 u1 = *(const uint2*)(val + (size_t)s1 * 128 + q * 4);
        float2 a0 = __half22float2(*(__half2*)&u0.x);
        float2 a1 = __half22float2(*(__half2*)&u0.y);
        float2 c0 = __half22float2(*(__half2*)&u1.x);
        float2 c1 = __half22float2(*(__half2*)&u1.y);
        A.x += a0.x; A.y += a0.y; A.z += a1.x; A.w += a1.y;
        B.x += c0.x; B.y += c0.y; B.z += c1.x; B.w += c1.y;
    }
    if (e < end) {
        int s = __ldg(&g_eidx[e]);
        uint2 u = *(const uint2*)(val + (size_t)s * 128 + q * 4);
        float2 a0 = __half22float2(*(__half2*)&u.x);
        float2 a1 = __half22float2(*(__half2*)&u.y);
        A.x += a0.x; A.y += a0.y; A.z += a1.x; A.w += a1.y;
    }
    float4 acc;
    acc.x = A.x + B.x; acc.y = A.y + B.y; acc.z = A.z + B.z; acc.w = A.w + B.w;
    acc.x += __shfl_xor_sync(0xffffffffu, acc.x, 16);
    acc.y += __shfl_xor_sync(0xffffffffu, acc.y, 16);
    acc.z += __shfl_xor_sync(0xffffffffu, acc.z, 16);
    acc.w += __shfl_xor_sync(0xffffffffu, acc.w, 16);

    if (hs == 0) {
        float r = g_rinv[node];
        if (layer == 0) {
            uint2 ux = *(const uint2*)(g_yx + (size_t)node * 128 + 64 + q * 4);
            float2 x0 = __half22float2(*(__half2*)&ux.x);
            float2 x1 = __half22float2(*(__half2*)&ux.y);
            float4 bb = __ldg((const float4*)b1 + q);
            float h0 = fmaxf(fmaf(acc.x, r, bb.x + x0.x), 0.f);
            float h1 = fmaxf(fmaf(acc.y, r, bb.y + x0.y), 0.f);
            float h2 = fmaxf(fmaf(acc.z, r, bb.z + x1.x), 0.f);
            float h3 = fmaxf(fmaf(acc.w, r, bb.w + x1.y), 0.f);
            uint2 st;
            *(__half2*)&st.x = __floats2half2_rn(h0, h1);
            *(__half2*)&st.y = __floats2half2_rn(h2, h3);
            *(uint2*)(g_cat + (size_t)node * 128 + 64 + q * 4) = st;
        } else {
            uint2 st;
            *(__half2*)&st.x = __floats2half2_rn(acc.x * r, acc.y * r);
            *(__half2*)&st.y = __floats2half2_rn(acc.z * r, acc.w * r);
            *(uint2*)(g_cat + (size_t)node * 128 + q * 4) = st;
        }
    }
}

// ---------------------------------------------------------------------------
extern "C" void kernel_launch(void* const* d_in, const int* in_sizes, int n_in,
                              void* d_out, int out_size) {
    const float* x   = (const float*)d_in[0];
    const int*   ei  = (const int*)d_in[1];     // int32 edge_index [2, E]
    const float* w1l = (const float*)d_in[2];
    const float* b1  = (const float*)d_in[3];
    const float* w1r = (const float*)d_in[4];
    const float* w2l = (const float*)d_in[5];
    const float* b2  = (const float*)d_in[6];
    const float* w2r = (const float*)d_in[7];
    float* out = (float*)d_out;

    int E = in_sizes[1] / 2;
    const int* src = ei;
    const int* dst = ei + E;

    int mgrid = (NN + BM - 1) / BM;   // 782

    static bool attr_done = false;
    if (!attr_done) {
        cudaFuncSetAttribute(k_mm, cudaFuncAttributeMaxDynamicSharedMemorySize,
                             MM_SMEM);
        attr_done = true;
    }

    k_init<<<(NN + 511) / 512, 512>>>();
    k_deg <<<(E + 255) / 256, 256>>>(dst, E);
    k_prepw<<<128, 256>>>(w1l, w1r, w2l, w2r);
    // Layer-1 GEMM as launch #4 (independent of CSR; lands in profiler window)
    k_mm<<<mgrid, 256, MM_SMEM>>>(x, nullptr, nullptr, NN, 0);
    k_scan_part<<<NPART, SCAN_B>>>();
    k_scan_top <<<1, 512>>>();
    k_scan_off <<<NPART, SCAN_B>>>();
    k_fill<<<(E + 255) / 256, 256>>>(src, dst, E);

    k_agg<<<(NN + 7) / 8, 256>>>(b1, 0);
    k_agg<<<(NN + 7) / 8, 256>>>(b1, 1);

    // Layer-2 GEMM (+bias) straight to output
    k_mm<<<mgrid, 256, MM_SMEM>>>(nullptr, b2, out, NN, 1);
}